// round 9
// baseline (speedup 1.0000x reference)
#include <cuda_runtime.h>
#include <cuda_bf16.h>
#include <cstdint>
#include <cstddef>

#define T_TOK 200704          // 4096 * 49 tokens
#define DIMC  192
#define NHD   6
#define HDIM  32
#define NTOK  49
#define NQKV  576
#define SCALEA 0.17677669529663687f
#define BIAS_STRIDE 2404      // 49*49 padded to 16B multiple (floats)

// ---------------- device scratch (static; no runtime allocation) -------------
__device__ __nv_bfloat16 g_qkvh[(size_t)T_TOK * NQKV];   // [b][which][h][tok][d]
__device__ __nv_bfloat16 g_qkvl[(size_t)T_TOK * NQKV];
__device__ __nv_bfloat16 g_aoh[(size_t)T_TOK * DIMC];    // attn out hi [t][c]
__device__ __nv_bfloat16 g_aol[(size_t)T_TOK * DIMC];
__device__ __nv_bfloat16 g_wqkvT_h[NQKV * DIMC];
__device__ __nv_bfloat16 g_wqkvT_l[NQKV * DIMC];
__device__ __nv_bfloat16 g_wprojT_h[DIMC * DIMC];
__device__ __nv_bfloat16 g_wprojT_l[DIMC * DIMC];
__device__ float g_bias6[NHD * BIAS_STRIDE];

// ---------------- helpers ----------------------------------------------------
__device__ __forceinline__ uint32_t packbf(__nv_bfloat16 a, __nv_bfloat16 b) {
    __nv_bfloat162 t(a, b);
    return *reinterpret_cast<uint32_t*>(&t);
}

__device__ __forceinline__ void mma16816(float* c, const uint32_t* a,
                                         uint32_t b0, uint32_t b1) {
    asm volatile(
        "mma.sync.aligned.m16n8k16.row.col.f32.bf16.bf16.f32 "
        "{%0,%1,%2,%3},{%4,%5,%6,%7},{%8,%9},{%0,%1,%2,%3};"
        : "+f"(c[0]), "+f"(c[1]), "+f"(c[2]), "+f"(c[3])
        : "r"(a[0]), "r"(a[1]), "r"(a[2]), "r"(a[3]), "r"(b0), "r"(b1));
}

__device__ __forceinline__ void ldsm4(uint32_t* r, uint32_t addr) {
    asm volatile("ldmatrix.sync.aligned.m8n8.x4.shared.b16 {%0,%1,%2,%3}, [%4];"
                 : "=r"(r[0]), "=r"(r[1]), "=r"(r[2]), "=r"(r[3]) : "r"(addr));
}

__device__ __forceinline__ void ldsm4t(uint32_t* r, uint32_t addr) {
    asm volatile("ldmatrix.sync.aligned.m8n8.x4.trans.shared.b16 {%0,%1,%2,%3}, [%4];"
                 : "=r"(r[0]), "=r"(r[1]), "=r"(r[2]), "=r"(r[3]) : "r"(addr));
}

__device__ __forceinline__ void cpa16(uint32_t smem, const void* gptr) {
    asm volatile("cp.async.cg.shared.global [%0], [%1], 16;\n"
                 :: "r"(smem), "l"(gptr));
}
__device__ __forceinline__ void cp_commit() {
    asm volatile("cp.async.commit_group;\n" ::: "memory");
}
__device__ __forceinline__ void cp_wait0() {
    asm volatile("cp.async.wait_group 0;\n" ::: "memory");
}

__device__ __forceinline__ uint32_t s2u(const void* p) {
    return (uint32_t)__cvta_generic_to_shared(p);
}

// ---------------- prep: split weights + pre-gather bias ----------------------
__global__ void prep_kernel(const float* __restrict__ qkv_w,
                            const float* __restrict__ proj_w,
                            const float* __restrict__ bias_table,
                            const int*   __restrict__ rel_idx) {
    const int n1 = NQKV * DIMC, n2 = DIMC * DIMC, n3 = NHD * NTOK * NTOK;
    for (int i = blockIdx.x * blockDim.x + threadIdx.x; i < n1 + n2 + n3;
         i += gridDim.x * blockDim.x) {
        if (i < n1) {
            int n = i / DIMC, k = i % DIMC;
            float w = qkv_w[k * NQKV + n];
            __nv_bfloat16 h = __float2bfloat16(w);
            g_wqkvT_h[i] = h;
            g_wqkvT_l[i] = __float2bfloat16(w - __bfloat162float(h));
        } else if (i < n1 + n2) {
            int j = i - n1;
            int n = j / DIMC, k = j % DIMC;
            float w = proj_w[k * DIMC + n];
            __nv_bfloat16 h = __float2bfloat16(w);
            g_wprojT_h[j] = h;
            g_wprojT_l[j] = __float2bfloat16(w - __bfloat162float(h));
        } else {
            int j = i - n1 - n2;
            int h6 = j / (NTOK * NTOK);
            int rc = j % (NTOK * NTOK);
            g_bias6[h6 * BIAS_STRIDE + rc] = bias_table[rel_idx[rc] * NHD + h6];
        }
    }
}

// ---------------- GEMM: C[128-row tile, Nc] = A[128,192] * W^T + bias --------
// A (hi/lo bf16) staged once; B in 64-col chunks, hi/lo, double-buffered.
// 8 warps = 4(M) x 2(N); warp tile 32M x 32N; 8 ldmatrix.x4 -> 24 MMAs per kk.
// mode 0: A = x fp32 (split in prologue), C -> g_qkvh/l scatter, 9 chunks
// mode 1: A = g_aoh/g_aol (cp.async),     C -> out fp32,         3 chunks
#define GBM   128
#define GSTR  200                        // smem row stride in halves
#define SM_A  (GBM * GSTR)               // 25600 halves per A buffer
#define SM_B  (64 * GSTR)                // 12800 halves per B buffer
#define GEMM_SMEM ((2 * SM_A + 4 * SM_B) * 2)   // 204800 bytes

__global__ __launch_bounds__(256, 1)
void gemm_kernel(const float* __restrict__ Ax, float* __restrict__ Cout,
                 const float* __restrict__ bias, int nChunks, int mode) {
    extern __shared__ __nv_bfloat16 smb[];
    __nv_bfloat16* Ah  = smb;
    __nv_bfloat16* Al  = smb + SM_A;
    __nv_bfloat16* B0h = smb + 2 * SM_A;
    __nv_bfloat16* B0l = B0h + SM_B;
    __nv_bfloat16* B1h = B0l + SM_B;
    __nv_bfloat16* B1l = B1h + SM_B;

    const __nv_bfloat16* Bgh = mode ? g_wprojT_h : g_wqkvT_h;
    const __nv_bfloat16* Bgl = mode ? g_wprojT_l : g_wqkvT_l;

    const int tid = threadIdx.x;
    const size_t rbase = (size_t)blockIdx.x * GBM;

    // B chunk 0 -> buffer 0 (async)
    for (int i = tid; i < 64 * 24; i += 256) {
        int row = i / 24, j = i % 24;
        const size_t go = (size_t)row * DIMC + j * 8;
        cpa16(s2u(B0h + row * GSTR + j * 8), Bgh + go);
        cpa16(s2u(B0l + row * GSTR + j * 8), Bgl + go);
    }
    cp_commit();

    if (mode == 0) {
        // A: fp32 x, convert+split into smem
        for (int i = tid; i < GBM * 48; i += 256) {
            int row = i / 48, j = i % 48;
            float4 v = *(const float4*)(Ax + (rbase + row) * DIMC + j * 4);
            __nv_bfloat16 h0 = __float2bfloat16(v.x), h1 = __float2bfloat16(v.y);
            __nv_bfloat16 h2 = __float2bfloat16(v.z), h3 = __float2bfloat16(v.w);
            __nv_bfloat16 l0 = __float2bfloat16(v.x - __bfloat162float(h0));
            __nv_bfloat16 l1 = __float2bfloat16(v.y - __bfloat162float(h1));
            __nv_bfloat16 l2 = __float2bfloat16(v.z - __bfloat162float(h2));
            __nv_bfloat16 l3 = __float2bfloat16(v.w - __bfloat162float(h3));
            *(uint2*)(Ah + row * GSTR + j * 4) = make_uint2(packbf(h0, h1), packbf(h2, h3));
            *(uint2*)(Al + row * GSTR + j * 4) = make_uint2(packbf(l0, l1), packbf(l2, l3));
        }
    } else {
        for (int i = tid; i < GBM * 24; i += 256) {
            int row = i / 24, j = i % 24;
            const size_t go = (rbase + row) * DIMC + j * 8;
            cpa16(s2u(Ah + row * GSTR + j * 8), g_aoh + go);
            cpa16(s2u(Al + row * GSTR + j * 8), g_aol + go);
        }
        cp_commit();
    }
    cp_wait0();
    __syncthreads();

    const int lane = tid & 31, warp = tid >> 5;
    const int g = lane >> 2, tg = lane & 3;
    const int m0 = (warp >> 1) * 32;        // 4 warps over M=128
    const int n0 = (warp & 1) * 32;         // 2 warps over 64-col chunk

    const int aRow = m0 + (lane & 15);
    const int aK   = (lane >> 4) * 8;
    const int b4Row = n0 + (lane & 7) + ((lane >> 4) << 3);
    const int bK    = ((lane >> 3) & 1) * 8;

    const uint32_t aBaseH = s2u(Ah + aRow * GSTR + aK);
    const uint32_t aBaseL = aBaseH + SM_A * 2;
    const uint32_t bOff   = (uint32_t)(b4Row * GSTR + bK) * 2;
    const uint32_t b0H = s2u(B0h) + bOff, b0L = s2u(B0l) + bOff;
    const uint32_t b1H = s2u(B1h) + bOff, b1L = s2u(B1l) + bOff;
    const uint32_t ROW16 = 16 * GSTR * 2;   // +16 rows in bytes

    for (int c = 0; c < nChunks; c++) {
        // prefetch next B chunk into the other buffer (disjoint; no sync needed)
        if (c + 1 < nChunks) {
            __nv_bfloat16* nh = ((c + 1) & 1) ? B1h : B0h;
            __nv_bfloat16* nl = ((c + 1) & 1) ? B1l : B0l;
            for (int i = tid; i < 64 * 24; i += 256) {
                int row = i / 24, j = i % 24;
                const size_t go = (size_t)((c + 1) * 64 + row) * DIMC + j * 8;
                cpa16(s2u(nh + row * GSTR + j * 8), Bgh + go);
                cpa16(s2u(nl + row * GSTR + j * 8), Bgl + go);
            }
            cp_commit();
        }

        float acc[2][4][4];
#pragma unroll
        for (int mt = 0; mt < 2; mt++)
#pragma unroll
            for (int nt = 0; nt < 4; nt++)
#pragma unroll
                for (int r = 0; r < 4; r++) acc[mt][nt][r] = 0.f;

        const uint32_t bH = (c & 1) ? b1H : b0H;
        const uint32_t bL = (c & 1) ? b1L : b0L;

#pragma unroll
        for (int kk = 0; kk < 12; kk++) {
            uint32_t ah[8], al[8], bh[8], bl[8];
            ldsm4(ah,     aBaseH + kk * 32);
            ldsm4(ah + 4, aBaseH + ROW16 + kk * 32);
            ldsm4(al,     aBaseL + kk * 32);
            ldsm4(al + 4, aBaseL + ROW16 + kk * 32);
            ldsm4(bh,     bH + kk * 32);
            ldsm4(bh + 4, bH + ROW16 + kk * 32);
            ldsm4(bl,     bL + kk * 32);
            ldsm4(bl + 4, bL + ROW16 + kk * 32);
#pragma unroll
            for (int mt = 0; mt < 2; mt++)
#pragma unroll
                for (int nt = 0; nt < 4; nt++) {
                    mma16816(acc[mt][nt], ah + 4 * mt, bh[2 * nt], bh[2 * nt + 1]);
                    mma16816(acc[mt][nt], al + 4 * mt, bh[2 * nt], bh[2 * nt + 1]);
                    mma16816(acc[mt][nt], ah + 4 * mt, bl[2 * nt], bl[2 * nt + 1]);
                }
        }

        // epilogue for chunk c (cp.async for c+1 still in flight)
        if (mode == 0) {
            const int which = c / 3;
            const int hb = (c % 3) * 2;
#pragma unroll
            for (int mt = 0; mt < 2; mt++)
#pragma unroll
                for (int rr = 0; rr < 2; rr++) {
                    size_t r = rbase + m0 + mt * 16 + g + rr * 8;
                    unsigned bwin = (unsigned)(r / NTOK), tok = (unsigned)(r % NTOK);
                    size_t ob = ((size_t)(bwin * 3 + which) * NHD) * NTOK * HDIM
                                + (size_t)tok * HDIM;
#pragma unroll
                    for (int nt = 0; nt < 4; nt++) {
                        int local = n0 + nt * 8 + tg * 2;
                        int hh = hb + (local >> 5), d = local & 31;
                        float v0 = acc[mt][nt][rr * 2 + 0] + bias[c * 64 + local];
                        float v1 = acc[mt][nt][rr * 2 + 1] + bias[c * 64 + local + 1];
                        __nv_bfloat16 h0 = __float2bfloat16(v0);
                        __nv_bfloat16 h1 = __float2bfloat16(v1);
                        size_t off = ob + (size_t)hh * NTOK * HDIM + d;
                        *(uint32_t*)(g_qkvh + off) = packbf(h0, h1);
                        *(uint32_t*)(g_qkvl + off) =
                            packbf(__float2bfloat16(v0 - __bfloat162float(h0)),
                                   __float2bfloat16(v1 - __bfloat162float(h1)));
                    }
                }
        } else {
#pragma unroll
            for (int mt = 0; mt < 2; mt++)
#pragma unroll
                for (int rr = 0; rr < 2; rr++) {
                    size_t r = rbase + m0 + mt * 16 + g + rr * 8;
#pragma unroll
                    for (int nt = 0; nt < 4; nt++) {
                        int col = c * 64 + n0 + nt * 8 + tg * 2;
                        *(float2*)(Cout + r * DIMC + col) =
                            make_float2(acc[mt][nt][rr * 2 + 0] + bias[col],
                                        acc[mt][nt][rr * 2 + 1] + bias[col + 1]);
                    }
                }
        }

        if (c + 1 < nChunks) {
            cp_wait0();
            __syncthreads();
        }
    }
}

// ---------------- attention: one CTA per (2 windows, head) -------------------
#define ABUF 1960                 // halves per buffer
#define AB_B 3920                 // bytes per buffer
#define ATTN_SMEM (12 * AB_B + BIAS_STRIDE * 4)   // 56656 bytes

__global__ __launch_bounds__(256)
void attn_kernel() {
    extern __shared__ char dsm[];
    __nv_bfloat16* sQKV = (__nv_bfloat16*)dsm;
    float* sBias = (float*)(dsm + 12 * AB_B);

    const int b = blockIdx.x, h = blockIdx.y;   // b = window pair
    const int tid = threadIdx.x;
    const uint32_t sBase = s2u(sQKV);
    const uint32_t sBiasU = s2u(sBias);

    {
        const size_t slabStride = (size_t)NTOK * HDIM;               // 1568
        const float* biasg = g_bias6 + h * BIAS_STRIDE;
        for (int i = tid; i < 12 * 196 + 601; i += 256) {
            if (i < 12 * 196) {
                int s = i / 196, j = i - s * 196;
                int wi = s / 6, sb2 = s - wi * 6;
                int which = sb2 >> 1;
                const size_t base =
                    ((size_t)(b * 2 + wi) * 3 * NHD + h) * slabStride
                    + (size_t)which * NHD * slabStride;
                const __nv_bfloat16* src =
                    ((sb2 & 1) ? g_qkvl : g_qkvh) + base + j * 8;
                cpa16(sBase + s * AB_B + (j >> 2) * 80 + (j & 3) * 16, src);
            } else {
                int j = i - 12 * 196;
                cpa16(sBiasU + j * 16, biasg + j * 4);
            }
        }
        cp_commit();
    }

    const int lane = tid & 31, w = tid >> 5;
    const int wi = w >> 2, wl = w & 3;
    const int g = lane >> 2, tg = lane & 3;
    const uint32_t qkvB = sBase + wi * (6 * AB_B);

    const int qRow = wl * 16 + (lane & 15);
    const uint32_t qOff = (uint32_t)(min(qRow, 48) * 80 + (lane >> 4) * 16);
    const int kR = (lane & 7) + ((lane >> 4) << 3);
    const int kC = ((lane >> 3) & 1) * 16;
    const int vR0 = (lane & 7) + (((lane >> 3) & 1) << 3);
    const int vC = (lane >> 4) * 16;

    cp_wait0();
    __syncthreads();

    float s[8][4];
#pragma unroll
    for (int nt = 0; nt < 8; nt++)
#pragma unroll
        for (int r = 0; r < 4; r++) s[nt][r] = 0.f;

#pragma unroll
    for (int part = 0; part < 3; part++) {
        const uint32_t qB = qkvB + ((part == 1) ? AB_B : 0) + qOff;
        const uint32_t kB = qkvB + 2 * AB_B + ((part == 2) ? AB_B : 0);
#pragma unroll
        for (int kk = 0; kk < 2; kk++) {
            uint32_t a[4];
            ldsm4(a, qB + kk * 32);
#pragma unroll
            for (int p = 0; p < 4; p++) {
                uint32_t bfr[4];
                ldsm4(bfr, kB + (uint32_t)(min(p * 16 + kR, 48) * 80 + kC) + kk * 32);
                mma16816(s[2 * p], a, bfr[0], bfr[1]);
                mma16816(s[2 * p + 1], a, bfr[2], bfr[3]);
            }
        }
    }

    const int r0 = wl * 16 + g, r1 = r0 + 8;
#pragma unroll
    for (int nt = 0; nt < 8; nt++) {
#pragma unroll
        for (int j = 0; j < 2; j++) {
            int col = nt * 8 + tg * 2 + j;
            if (col < NTOK) {
                s[nt][j]     = s[nt][j]     * SCALEA + (r0 < NTOK ? sBias[r0 * NTOK + col] : 0.f);
                s[nt][2 + j] = s[nt][2 + j] * SCALEA + (r1 < NTOK ? sBias[r1 * NTOK + col] : 0.f);
            } else {
                s[nt][j] = -1e30f;
                s[nt][2 + j] = -1e30f;
            }
        }
    }

    float m0 = -1e30f, m1 = -1e30f;
#pragma unroll
    for (int nt = 0; nt < 8; nt++) {
        m0 = fmaxf(m0, fmaxf(s[nt][0], s[nt][1]));
        m1 = fmaxf(m1, fmaxf(s[nt][2], s[nt][3]));
    }
    m0 = fmaxf(m0, __shfl_xor_sync(0xffffffffu, m0, 1));
    m0 = fmaxf(m0, __shfl_xor_sync(0xffffffffu, m0, 2));
    m1 = fmaxf(m1, __shfl_xor_sync(0xffffffffu, m1, 1));
    m1 = fmaxf(m1, __shfl_xor_sync(0xffffffffu, m1, 2));
    float d0 = 0.f, d1 = 0.f;
#pragma unroll
    for (int nt = 0; nt < 8; nt++) {
        s[nt][0] = __expf(s[nt][0] - m0); d0 += s[nt][0];
        s[nt][1] = __expf(s[nt][1] - m0); d0 += s[nt][1];
        s[nt][2] = __expf(s[nt][2] - m1); d1 += s[nt][2];
        s[nt][3] = __expf(s[nt][3] - m1); d1 += s[nt][3];
    }
    d0 += __shfl_xor_sync(0xffffffffu, d0, 1);
    d0 += __shfl_xor_sync(0xffffffffu, d0, 2);
    d1 += __shfl_xor_sync(0xffffffffu, d1, 1);
    d1 += __shfl_xor_sync(0xffffffffu, d1, 2);
    const float inv0 = 1.f / d0, inv1 = 1.f / d1;

    uint32_t aPh[4][4], aPl[4][4];
#pragma unroll
    for (int kc = 0; kc < 4; kc++) {
#pragma unroll
        for (int t2 = 0; t2 < 2; t2++) {
            int tile = 2 * kc + t2;
            float p0 = s[tile][0] * inv0, p1 = s[tile][1] * inv0;
            float p2 = s[tile][2] * inv1, p3 = s[tile][3] * inv1;
            __nv_bfloat16 h0 = __float2bfloat16(p0), h1 = __float2bfloat16(p1);
            __nv_bfloat16 h2 = __float2bfloat16(p2), h3 = __float2bfloat16(p3);
            aPh[kc][t2]     = packbf(h0, h1);
            aPh[kc][t2 + 2] = packbf(h2, h3);
            aPl[kc][t2]     = packbf(__float2bfloat16(p0 - __bfloat162float(h0)),
                                     __float2bfloat16(p1 - __bfloat162float(h1)));
            aPl[kc][t2 + 2] = packbf(__float2bfloat16(p2 - __bfloat162float(h2)),
                                     __float2bfloat16(p3 - __bfloat162float(h3)));
        }
    }
#pragma unroll
    for (int kc = 0; kc < 4; kc++) {
        uint32_t t = aPh[kc][1]; aPh[kc][1] = aPh[kc][2]; aPh[kc][2] = t;
        t = aPl[kc][1]; aPl[kc][1] = aPl[kc][2]; aPl[kc][2] = t;
    }

    float o[4][4];
#pragma unroll
    for (int nt = 0; nt < 4; nt++)
#pragma unroll
        for (int r = 0; r < 4; r++) o[nt][r] = 0.f;

#pragma unroll
    for (int part = 0; part < 3; part++) {
        const uint32_t (*Ap)[4] = (part == 1) ? aPl : aPh;
        const uint32_t vB = qkvB + 4 * AB_B + ((part == 2) ? AB_B : 0);
#pragma unroll
        for (int kc = 0; kc < 4; kc++) {
            const uint32_t rowOff = (uint32_t)(min(vR0 + kc * 16, 48) * 80 + vC);
#pragma unroll
            for (int dh = 0; dh < 2; dh++) {
                uint32_t bv[4];
                ldsm4t(bv, vB + rowOff + dh * 32);
                mma16816(o[dh * 2 + 0], Ap[kc], bv[0], bv[1]);
                mma16816(o[dh * 2 + 1], Ap[kc], bv[2], bv[3]);
            }
        }
    }

    const size_t bw = (size_t)(b * 2 + wi);
#pragma unroll
    for (int nt = 0; nt < 4; nt++) {
        int d = h * HDIM + nt * 8 + tg * 2;
        if (r0 < NTOK) {
            size_t off = (bw * NTOK + r0) * DIMC + d;
            __nv_bfloat16 h0 = __float2bfloat16(o[nt][0]);
            __nv_bfloat16 h1 = __float2bfloat16(o[nt][1]);
            *(uint32_t*)(g_aoh + off) = packbf(h0, h1);
            *(uint32_t*)(g_aol + off) =
                packbf(__float2bfloat16(o[nt][0] - __bfloat162float(h0)),
                       __float2bfloat16(o[nt][1] - __bfloat162float(h1)));
        }
        if (r1 < NTOK) {
            size_t off = (bw * NTOK + r1) * DIMC + d;
            __nv_bfloat16 h2 = __float2bfloat16(o[nt][2]);
            __nv_bfloat16 h3 = __float2bfloat16(o[nt][3]);
            *(uint32_t*)(g_aoh + off) = packbf(h2, h3);
            *(uint32_t*)(g_aol + off) =
                packbf(__float2bfloat16(o[nt][2] - __bfloat162float(h2)),
                       __float2bfloat16(o[nt][3] - __bfloat162float(h3)));
        }
    }
}

// ---------------- launch ------------------------------------------------------
extern "C" void kernel_launch(void* const* d_in, const int* in_sizes, int n_in,
                              void* d_out, int out_size) {
    const float* x          = (const float*)d_in[0];
    const float* qkv_w      = (const float*)d_in[1];
    const float* qkv_b      = (const float*)d_in[2];
    const float* proj_w     = (const float*)d_in[3];
    const float* proj_b     = (const float*)d_in[4];
    const float* bias_table = (const float*)d_in[5];
    const int*   rel_idx    = (const int*)d_in[6];
    float* out = (float*)d_out;

    static bool attr_set = false;
    if (!attr_set) {
        cudaFuncSetAttribute(gemm_kernel, cudaFuncAttributeMaxDynamicSharedMemorySize,
                             GEMM_SMEM);
        cudaFuncSetAttribute(attn_kernel, cudaFuncAttributeMaxDynamicSharedMemorySize,
                             ATTN_SMEM);
        attr_set = true;
    }

    prep_kernel<<<640, 256>>>(qkv_w, proj_w, bias_table, rel_idx);

    gemm_kernel<<<T_TOK / GBM, 256, GEMM_SMEM>>>(x, nullptr, qkv_b, 9, 0);

    dim3 g2(2048, NHD);
    attn_kernel<<<g2, 256, ATTN_SMEM>>>();

    gemm_kernel<<<T_TOK / GBM, 256, GEMM_SMEM>>>(nullptr, out, proj_b, 3, 1);
}

// round 10
// speedup vs baseline: 1.4780x; 1.4780x over previous
#include <cuda_runtime.h>
#include <cuda_bf16.h>
#include <cstdint>
#include <cstddef>

#define T_TOK 200704          // 4096 * 49 tokens
#define DIMC  192
#define NHD   6
#define HDIM  32
#define NTOK  49
#define NQKV  576
#define SCALEA 0.17677669529663687f
#define BIAS_STRIDE 2404      // 49*49 padded to 16B multiple (floats)

// ---------------- device scratch (static; no runtime allocation) -------------
__device__ __nv_bfloat16 g_qkvh[(size_t)T_TOK * NQKV];   // [b][which][h][tok][d]
__device__ __nv_bfloat16 g_qkvl[(size_t)T_TOK * NQKV];
__device__ __nv_bfloat16 g_aoh[(size_t)T_TOK * DIMC];    // attn out hi [t][c]
__device__ __nv_bfloat16 g_aol[(size_t)T_TOK * DIMC];
__device__ __nv_bfloat16 g_wqkvT_h[NQKV * DIMC];
__device__ __nv_bfloat16 g_wqkvT_l[NQKV * DIMC];
__device__ __nv_bfloat16 g_wprojT_h[DIMC * DIMC];
__device__ __nv_bfloat16 g_wprojT_l[DIMC * DIMC];
__device__ float g_bias6[NHD * BIAS_STRIDE];

// ---------------- helpers ----------------------------------------------------
__device__ __forceinline__ uint32_t packbf(__nv_bfloat16 a, __nv_bfloat16 b) {
    __nv_bfloat162 t(a, b);
    return *reinterpret_cast<uint32_t*>(&t);
}

__device__ __forceinline__ void mma16816(float* c, const uint32_t* a,
                                         uint32_t b0, uint32_t b1) {
    asm volatile(
        "mma.sync.aligned.m16n8k16.row.col.f32.bf16.bf16.f32 "
        "{%0,%1,%2,%3},{%4,%5,%6,%7},{%8,%9},{%0,%1,%2,%3};"
        : "+f"(c[0]), "+f"(c[1]), "+f"(c[2]), "+f"(c[3])
        : "r"(a[0]), "r"(a[1]), "r"(a[2]), "r"(a[3]), "r"(b0), "r"(b1));
}

__device__ __forceinline__ void ldsm4(uint32_t* r, uint32_t addr) {
    asm volatile("ldmatrix.sync.aligned.m8n8.x4.shared.b16 {%0,%1,%2,%3}, [%4];"
                 : "=r"(r[0]), "=r"(r[1]), "=r"(r[2]), "=r"(r[3]) : "r"(addr));
}

__device__ __forceinline__ void ldsm4t(uint32_t* r, uint32_t addr) {
    asm volatile("ldmatrix.sync.aligned.m8n8.x4.trans.shared.b16 {%0,%1,%2,%3}, [%4];"
                 : "=r"(r[0]), "=r"(r[1]), "=r"(r[2]), "=r"(r[3]) : "r"(addr));
}

__device__ __forceinline__ void cpa16(uint32_t smem, const void* gptr) {
    asm volatile("cp.async.cg.shared.global [%0], [%1], 16;\n"
                 :: "r"(smem), "l"(gptr));
}
__device__ __forceinline__ void cp_commit() {
    asm volatile("cp.async.commit_group;\n" ::: "memory");
}
__device__ __forceinline__ void cp_wait0() {
    asm volatile("cp.async.wait_group 0;\n" ::: "memory");
}

__device__ __forceinline__ uint32_t s2u(const void* p) {
    return (uint32_t)__cvta_generic_to_shared(p);
}

// ---------------- prep: split weights + pre-gather bias ----------------------
__global__ void prep_kernel(const float* __restrict__ qkv_w,
                            const float* __restrict__ proj_w,
                            const float* __restrict__ bias_table,
                            const int*   __restrict__ rel_idx) {
    const int n1 = NQKV * DIMC, n2 = DIMC * DIMC, n3 = NHD * NTOK * NTOK;
    for (int i = blockIdx.x * blockDim.x + threadIdx.x; i < n1 + n2 + n3;
         i += gridDim.x * blockDim.x) {
        if (i < n1) {
            int n = i / DIMC, k = i % DIMC;
            float w = qkv_w[k * NQKV + n];
            __nv_bfloat16 h = __float2bfloat16(w);
            g_wqkvT_h[i] = h;
            g_wqkvT_l[i] = __float2bfloat16(w - __bfloat162float(h));
        } else if (i < n1 + n2) {
            int j = i - n1;
            int n = j / DIMC, k = j % DIMC;
            float w = proj_w[k * DIMC + n];
            __nv_bfloat16 h = __float2bfloat16(w);
            g_wprojT_h[j] = h;
            g_wprojT_l[j] = __float2bfloat16(w - __bfloat162float(h));
        } else {
            int j = i - n1 - n2;
            int h6 = j / (NTOK * NTOK);
            int rc = j % (NTOK * NTOK);
            g_bias6[h6 * BIAS_STRIDE + rc] = bias_table[rel_idx[rc] * NHD + h6];
        }
    }
}

// ---------------- GEMM: C[64-row tile, Nc] = A[64,192] * W^T + bias ----------
// A (hi/lo bf16) resident; B in 64-col chunks, hi/lo, single buffer (reloaded
// after the MMA loop; epilogue overlaps the in-flight cp.async).
// 4 warps = 2(M) x 2(N); warp tile 32M x 32N; 8 ldmatrix.x4 -> 24 MMAs per kk.
// mode 0: A = x fp32 (split in prologue), C -> g_qkvh/l scatter, 9 chunks
// mode 1: A = g_aoh/g_aol (cp.async),     C -> out fp32,         3 chunks
#define GBM   64
#define GSTR  200                        // smem row stride in halves
#define SM_A  (GBM * GSTR)               // 12800 halves per A buffer
#define SM_B  (64 * GSTR)                // 12800 halves per B buffer
#define GEMM_SMEM ((2 * SM_A + 2 * SM_B) * 2)   // 102400 bytes

__global__ __launch_bounds__(128, 2)
void gemm_kernel(const float* __restrict__ Ax, float* __restrict__ Cout,
                 const float* __restrict__ bias, int nChunks, int mode) {
    extern __shared__ __nv_bfloat16 smb[];
    __nv_bfloat16* Ah = smb;
    __nv_bfloat16* Al = smb + SM_A;
    __nv_bfloat16* Bh = smb + 2 * SM_A;
    __nv_bfloat16* Bl = Bh + SM_B;

    const __nv_bfloat16* Bgh = mode ? g_wprojT_h : g_wqkvT_h;
    const __nv_bfloat16* Bgl = mode ? g_wprojT_l : g_wqkvT_l;

    const int tid = threadIdx.x;
    const size_t rbase = (size_t)blockIdx.x * GBM;

    // B chunk 0 (async)
    for (int i = tid; i < 64 * 24; i += 128) {
        int row = i / 24, j = i % 24;
        const size_t go = (size_t)row * DIMC + j * 8;
        cpa16(s2u(Bh + row * GSTR + j * 8), Bgh + go);
        cpa16(s2u(Bl + row * GSTR + j * 8), Bgl + go);
    }
    cp_commit();

    if (mode == 0) {
        // A: fp32 x, convert+split into smem
        for (int i = tid; i < GBM * 48; i += 128) {
            int row = i / 48, j = i % 48;
            float4 v = *(const float4*)(Ax + (rbase + row) * DIMC + j * 4);
            __nv_bfloat16 h0 = __float2bfloat16(v.x), h1 = __float2bfloat16(v.y);
            __nv_bfloat16 h2 = __float2bfloat16(v.z), h3 = __float2bfloat16(v.w);
            __nv_bfloat16 l0 = __float2bfloat16(v.x - __bfloat162float(h0));
            __nv_bfloat16 l1 = __float2bfloat16(v.y - __bfloat162float(h1));
            __nv_bfloat16 l2 = __float2bfloat16(v.z - __bfloat162float(h2));
            __nv_bfloat16 l3 = __float2bfloat16(v.w - __bfloat162float(h3));
            *(uint2*)(Ah + row * GSTR + j * 4) = make_uint2(packbf(h0, h1), packbf(h2, h3));
            *(uint2*)(Al + row * GSTR + j * 4) = make_uint2(packbf(l0, l1), packbf(l2, l3));
        }
    } else {
        for (int i = tid; i < GBM * 24; i += 128) {
            int row = i / 24, j = i % 24;
            const size_t go = (rbase + row) * DIMC + j * 8;
            cpa16(s2u(Ah + row * GSTR + j * 8), g_aoh + go);
            cpa16(s2u(Al + row * GSTR + j * 8), g_aol + go);
        }
        cp_commit();
    }
    cp_wait0();
    __syncthreads();

    const int lane = tid & 31, warp = tid >> 5;
    const int g = lane >> 2, tg = lane & 3;
    const int m0 = (warp >> 1) * 32;        // 2 warps over M=64
    const int n0 = (warp & 1) * 32;         // 2 warps over 64-col chunk

    const int aRow = m0 + (lane & 15);
    const int aK   = (lane >> 4) * 8;
    const int b4Row = n0 + (lane & 7) + ((lane >> 4) << 3);
    const int bK    = ((lane >> 3) & 1) * 8;

    const uint32_t aBaseH = s2u(Ah + aRow * GSTR + aK);
    const uint32_t aBaseL = aBaseH + SM_A * 2;
    const uint32_t bBaseH = s2u(Bh + b4Row * GSTR + bK);
    const uint32_t bBaseL = bBaseH + SM_B * 2;
    const uint32_t ROW16 = 16 * GSTR * 2;   // +16 rows in bytes

    for (int c = 0; c < nChunks; c++) {
        float acc[2][4][4];
#pragma unroll
        for (int mt = 0; mt < 2; mt++)
#pragma unroll
            for (int nt = 0; nt < 4; nt++)
#pragma unroll
                for (int r = 0; r < 4; r++) acc[mt][nt][r] = 0.f;

#pragma unroll
        for (int kk = 0; kk < 12; kk++) {
            uint32_t ah[8], al[8], bh[8], bl[8];
            ldsm4(ah,     aBaseH + kk * 32);
            ldsm4(ah + 4, aBaseH + ROW16 + kk * 32);
            ldsm4(al,     aBaseL + kk * 32);
            ldsm4(al + 4, aBaseL + ROW16 + kk * 32);
            ldsm4(bh,     bBaseH + kk * 32);
            ldsm4(bh + 4, bBaseH + ROW16 + kk * 32);
            ldsm4(bl,     bBaseL + kk * 32);
            ldsm4(bl + 4, bBaseL + ROW16 + kk * 32);
#pragma unroll
            for (int mt = 0; mt < 2; mt++)
#pragma unroll
                for (int nt = 0; nt < 4; nt++) {
                    mma16816(acc[mt][nt], ah + 4 * mt, bh[2 * nt], bh[2 * nt + 1]);
                    mma16816(acc[mt][nt], al + 4 * mt, bh[2 * nt], bh[2 * nt + 1]);
                    mma16816(acc[mt][nt], ah + 4 * mt, bl[2 * nt], bl[2 * nt + 1]);
                }
        }
        __syncthreads();                    // all warps done reading B chunk c

        if (c + 1 < nChunks) {              // overwrite B with next chunk
            for (int i = tid; i < 64 * 24; i += 128) {
                int row = i / 24, j = i % 24;
                const size_t go = (size_t)((c + 1) * 64 + row) * DIMC + j * 8;
                cpa16(s2u(Bh + row * GSTR + j * 8), Bgh + go);
                cpa16(s2u(Bl + row * GSTR + j * 8), Bgl + go);
            }
            cp_commit();
        }

        // epilogue for chunk c (overlaps in-flight cp.async)
        if (mode == 0) {
            const int which = c / 3;
            const int hb = (c % 3) * 2;
#pragma unroll
            for (int mt = 0; mt < 2; mt++)
#pragma unroll
                for (int rr = 0; rr < 2; rr++) {
                    size_t r = rbase + m0 + mt * 16 + g + rr * 8;
                    unsigned bwin = (unsigned)(r / NTOK), tok = (unsigned)(r % NTOK);
                    size_t ob = ((size_t)(bwin * 3 + which) * NHD) * NTOK * HDIM
                                + (size_t)tok * HDIM;
#pragma unroll
                    for (int nt = 0; nt < 4; nt++) {
                        int local = n0 + nt * 8 + tg * 2;
                        int hh = hb + (local >> 5), d = local & 31;
                        float v0 = acc[mt][nt][rr * 2 + 0] + bias[c * 64 + local];
                        float v1 = acc[mt][nt][rr * 2 + 1] + bias[c * 64 + local + 1];
                        __nv_bfloat16 h0 = __float2bfloat16(v0);
                        __nv_bfloat16 h1 = __float2bfloat16(v1);
                        size_t off = ob + (size_t)hh * NTOK * HDIM + d;
                        *(uint32_t*)(g_qkvh + off) = packbf(h0, h1);
                        *(uint32_t*)(g_qkvl + off) =
                            packbf(__float2bfloat16(v0 - __bfloat162float(h0)),
                                   __float2bfloat16(v1 - __bfloat162float(h1)));
                    }
                }
        } else {
#pragma unroll
            for (int mt = 0; mt < 2; mt++)
#pragma unroll
                for (int rr = 0; rr < 2; rr++) {
                    size_t r = rbase + m0 + mt * 16 + g + rr * 8;
#pragma unroll
                    for (int nt = 0; nt < 4; nt++) {
                        int col = c * 64 + n0 + nt * 8 + tg * 2;
                        *(float2*)(Cout + r * DIMC + col) =
                            make_float2(acc[mt][nt][rr * 2 + 0] + bias[col],
                                        acc[mt][nt][rr * 2 + 1] + bias[col + 1]);
                    }
                }
        }

        if (c + 1 < nChunks) {
            cp_wait0();
            __syncthreads();
        }
    }
}

// ---------------- attention: one CTA per (2 windows, head) -------------------
#define ABUF 1960                 // halves per buffer
#define AB_B 3920                 // bytes per buffer
#define ATTN_SMEM (12 * AB_B + BIAS_STRIDE * 4)   // 56656 bytes

__global__ __launch_bounds__(256)
void attn_kernel() {
    extern __shared__ char dsm[];
    __nv_bfloat16* sQKV = (__nv_bfloat16*)dsm;
    float* sBias = (float*)(dsm + 12 * AB_B);

    const int b = blockIdx.x, h = blockIdx.y;   // b = window pair
    const int tid = threadIdx.x;
    const uint32_t sBase = s2u(sQKV);
    const uint32_t sBiasU = s2u(sBias);

    {
        const size_t slabStride = (size_t)NTOK * HDIM;               // 1568
        const float* biasg = g_bias6 + h * BIAS_STRIDE;
        for (int i = tid; i < 12 * 196 + 601; i += 256) {
            if (i < 12 * 196) {
                int s = i / 196, j = i - s * 196;
                int wi = s / 6, sb2 = s - wi * 6;
                int which = sb2 >> 1;
                const size_t base =
                    ((size_t)(b * 2 + wi) * 3 * NHD + h) * slabStride
                    + (size_t)which * NHD * slabStride;
                const __nv_bfloat16* src =
                    ((sb2 & 1) ? g_qkvl : g_qkvh) + base + j * 8;
                cpa16(sBase + s * AB_B + (j >> 2) * 80 + (j & 3) * 16, src);
            } else {
                int j = i - 12 * 196;
                cpa16(sBiasU + j * 16, biasg + j * 4);
            }
        }
        cp_commit();
    }

    const int lane = tid & 31, w = tid >> 5;
    const int wi = w >> 2, wl = w & 3;
    const int g = lane >> 2, tg = lane & 3;
    const uint32_t qkvB = sBase + wi * (6 * AB_B);

    const int qRow = wl * 16 + (lane & 15);
    const uint32_t qOff = (uint32_t)(min(qRow, 48) * 80 + (lane >> 4) * 16);
    const int kR = (lane & 7) + ((lane >> 4) << 3);
    const int kC = ((lane >> 3) & 1) * 16;
    const int vR0 = (lane & 7) + (((lane >> 3) & 1) << 3);
    const int vC = (lane >> 4) * 16;

    cp_wait0();
    __syncthreads();

    float s[8][4];
#pragma unroll
    for (int nt = 0; nt < 8; nt++)
#pragma unroll
        for (int r = 0; r < 4; r++) s[nt][r] = 0.f;

#pragma unroll
    for (int part = 0; part < 3; part++) {
        const uint32_t qB = qkvB + ((part == 1) ? AB_B : 0) + qOff;
        const uint32_t kB = qkvB + 2 * AB_B + ((part == 2) ? AB_B : 0);
#pragma unroll
        for (int kk = 0; kk < 2; kk++) {
            uint32_t a[4];
            ldsm4(a, qB + kk * 32);
#pragma unroll
            for (int p = 0; p < 4; p++) {
                uint32_t bfr[4];
                ldsm4(bfr, kB + (uint32_t)(min(p * 16 + kR, 48) * 80 + kC) + kk * 32);
                mma16816(s[2 * p], a, bfr[0], bfr[1]);
                mma16816(s[2 * p + 1], a, bfr[2], bfr[3]);
            }
        }
    }

    const int r0 = wl * 16 + g, r1 = r0 + 8;
#pragma unroll
    for (int nt = 0; nt < 8; nt++) {
#pragma unroll
        for (int j = 0; j < 2; j++) {
            int col = nt * 8 + tg * 2 + j;
            if (col < NTOK) {
                s[nt][j]     = s[nt][j]     * SCALEA + (r0 < NTOK ? sBias[r0 * NTOK + col] : 0.f);
                s[nt][2 + j] = s[nt][2 + j] * SCALEA + (r1 < NTOK ? sBias[r1 * NTOK + col] : 0.f);
            } else {
                s[nt][j] = -1e30f;
                s[nt][2 + j] = -1e30f;
            }
        }
    }

    float m0 = -1e30f, m1 = -1e30f;
#pragma unroll
    for (int nt = 0; nt < 8; nt++) {
        m0 = fmaxf(m0, fmaxf(s[nt][0], s[nt][1]));
        m1 = fmaxf(m1, fmaxf(s[nt][2], s[nt][3]));
    }
    m0 = fmaxf(m0, __shfl_xor_sync(0xffffffffu, m0, 1));
    m0 = fmaxf(m0, __shfl_xor_sync(0xffffffffu, m0, 2));
    m1 = fmaxf(m1, __shfl_xor_sync(0xffffffffu, m1, 1));
    m1 = fmaxf(m1, __shfl_xor_sync(0xffffffffu, m1, 2));
    float d0 = 0.f, d1 = 0.f;
#pragma unroll
    for (int nt = 0; nt < 8; nt++) {
        s[nt][0] = __expf(s[nt][0] - m0); d0 += s[nt][0];
        s[nt][1] = __expf(s[nt][1] - m0); d0 += s[nt][1];
        s[nt][2] = __expf(s[nt][2] - m1); d1 += s[nt][2];
        s[nt][3] = __expf(s[nt][3] - m1); d1 += s[nt][3];
    }
    d0 += __shfl_xor_sync(0xffffffffu, d0, 1);
    d0 += __shfl_xor_sync(0xffffffffu, d0, 2);
    d1 += __shfl_xor_sync(0xffffffffu, d1, 1);
    d1 += __shfl_xor_sync(0xffffffffu, d1, 2);
    const float inv0 = 1.f / d0, inv1 = 1.f / d1;

    uint32_t aPh[4][4], aPl[4][4];
#pragma unroll
    for (int kc = 0; kc < 4; kc++) {
#pragma unroll
        for (int t2 = 0; t2 < 2; t2++) {
            int tile = 2 * kc + t2;
            float p0 = s[tile][0] * inv0, p1 = s[tile][1] * inv0;
            float p2 = s[tile][2] * inv1, p3 = s[tile][3] * inv1;
            __nv_bfloat16 h0 = __float2bfloat16(p0), h1 = __float2bfloat16(p1);
            __nv_bfloat16 h2 = __float2bfloat16(p2), h3 = __float2bfloat16(p3);
            aPh[kc][t2]     = packbf(h0, h1);
            aPh[kc][t2 + 2] = packbf(h2, h3);
            aPl[kc][t2]     = packbf(__float2bfloat16(p0 - __bfloat162float(h0)),
                                     __float2bfloat16(p1 - __bfloat162float(h1)));
            aPl[kc][t2 + 2] = packbf(__float2bfloat16(p2 - __bfloat162float(h2)),
                                     __float2bfloat16(p3 - __bfloat162float(h3)));
        }
    }
#pragma unroll
    for (int kc = 0; kc < 4; kc++) {
        uint32_t t = aPh[kc][1]; aPh[kc][1] = aPh[kc][2]; aPh[kc][2] = t;
        t = aPl[kc][1]; aPl[kc][1] = aPl[kc][2]; aPl[kc][2] = t;
    }

    float o[4][4];
#pragma unroll
    for (int nt = 0; nt < 4; nt++)
#pragma unroll
        for (int r = 0; r < 4; r++) o[nt][r] = 0.f;

#pragma unroll
    for (int part = 0; part < 3; part++) {
        const uint32_t (*Ap)[4] = (part == 1) ? aPl : aPh;
        const uint32_t vB = qkvB + 4 * AB_B + ((part == 2) ? AB_B : 0);
#pragma unroll
        for (int kc = 0; kc < 4; kc++) {
            const uint32_t rowOff = (uint32_t)(min(vR0 + kc * 16, 48) * 80 + vC);
#pragma unroll
            for (int dh = 0; dh < 2; dh++) {
                uint32_t bv[4];
                ldsm4t(bv, vB + rowOff + dh * 32);
                mma16816(o[dh * 2 + 0], Ap[kc], bv[0], bv[1]);
                mma16816(o[dh * 2 + 1], Ap[kc], bv[2], bv[3]);
            }
        }
    }

    const size_t bw = (size_t)(b * 2 + wi);
#pragma unroll
    for (int nt = 0; nt < 4; nt++) {
        int d = h * HDIM + nt * 8 + tg * 2;
        if (r0 < NTOK) {
            size_t off = (bw * NTOK + r0) * DIMC + d;
            __nv_bfloat16 h0 = __float2bfloat16(o[nt][0]);
            __nv_bfloat16 h1 = __float2bfloat16(o[nt][1]);
            *(uint32_t*)(g_aoh + off) = packbf(h0, h1);
            *(uint32_t*)(g_aol + off) =
                packbf(__float2bfloat16(o[nt][0] - __bfloat162float(h0)),
                       __float2bfloat16(o[nt][1] - __bfloat162float(h1)));
        }
        if (r1 < NTOK) {
            size_t off = (bw * NTOK + r1) * DIMC + d;
            __nv_bfloat16 h2 = __float2bfloat16(o[nt][2]);
            __nv_bfloat16 h3 = __float2bfloat16(o[nt][3]);
            *(uint32_t*)(g_aoh + off) = packbf(h2, h3);
            *(uint32_t*)(g_aol + off) =
                packbf(__float2bfloat16(o[nt][2] - __bfloat162float(h2)),
                       __float2bfloat16(o[nt][3] - __bfloat162float(h3)));
        }
    }
}

// ---------------- launch ------------------------------------------------------
extern "C" void kernel_launch(void* const* d_in, const int* in_sizes, int n_in,
                              void* d_out, int out_size) {
    const float* x          = (const float*)d_in[0];
    const float* qkv_w      = (const float*)d_in[1];
    const float* qkv_b      = (const float*)d_in[2];
    const float* proj_w     = (const float*)d_in[3];
    const float* proj_b     = (const float*)d_in[4];
    const float* bias_table = (const float*)d_in[5];
    const int*   rel_idx    = (const int*)d_in[6];
    float* out = (float*)d_out;

    static bool attr_set = false;
    if (!attr_set) {
        cudaFuncSetAttribute(gemm_kernel, cudaFuncAttributeMaxDynamicSharedMemorySize,
                             GEMM_SMEM);
        cudaFuncSetAttribute(attn_kernel, cudaFuncAttributeMaxDynamicSharedMemorySize,
                             ATTN_SMEM);
        attr_set = true;
    }

    prep_kernel<<<640, 256>>>(qkv_w, proj_w, bias_table, rel_idx);

    gemm_kernel<<<T_TOK / GBM, 128, GEMM_SMEM>>>(x, nullptr, qkv_b, 9, 0);

    dim3 g2(2048, NHD);
    attn_kernel<<<g2, 256, ATTN_SMEM>>>();

    gemm_kernel<<<T_TOK / GBM, 128, GEMM_SMEM>>>(nullptr, out, proj_b, 3, 1);
}

// round 11
// speedup vs baseline: 1.4799x; 1.0013x over previous
#include <cuda_runtime.h>
#include <cuda_bf16.h>
#include <cstdint>
#include <cstddef>

#define T_TOK 200704          // 4096 * 49 tokens
#define DIMC  192
#define NHD   6
#define HDIM  32
#define NTOK  49
#define NQKV  576
#define SCALEA 0.17677669529663687f
#define BIAS_STRIDE 2404      // 49*49 padded to 16B multiple (floats)

// ---------------- device scratch (static; no runtime allocation) -------------
__device__ __nv_bfloat16 g_qkvh[(size_t)T_TOK * NQKV];   // [b][which][h][tok][d]
__device__ __nv_bfloat16 g_qkvl[(size_t)T_TOK * NQKV];
__device__ __nv_bfloat16 g_aoh[(size_t)T_TOK * DIMC];    // attn out hi [t][c]
__device__ __nv_bfloat16 g_aol[(size_t)T_TOK * DIMC];
__device__ __nv_bfloat16 g_wqkvT_h[NQKV * DIMC];
__device__ __nv_bfloat16 g_wqkvT_l[NQKV * DIMC];
__device__ __nv_bfloat16 g_wprojT_h[DIMC * DIMC];
__device__ __nv_bfloat16 g_wprojT_l[DIMC * DIMC];
__device__ float g_bias6[NHD * BIAS_STRIDE];

// ---------------- helpers ----------------------------------------------------
__device__ __forceinline__ uint32_t packbf(__nv_bfloat16 a, __nv_bfloat16 b) {
    __nv_bfloat162 t(a, b);
    return *reinterpret_cast<uint32_t*>(&t);
}

__device__ __forceinline__ void mma16816(float* c, const uint32_t* a,
                                         uint32_t b0, uint32_t b1) {
    asm volatile(
        "mma.sync.aligned.m16n8k16.row.col.f32.bf16.bf16.f32 "
        "{%0,%1,%2,%3},{%4,%5,%6,%7},{%8,%9},{%0,%1,%2,%3};"
        : "+f"(c[0]), "+f"(c[1]), "+f"(c[2]), "+f"(c[3])
        : "r"(a[0]), "r"(a[1]), "r"(a[2]), "r"(a[3]), "r"(b0), "r"(b1));
}

__device__ __forceinline__ void ldsm4(uint32_t* r, uint32_t addr) {
    asm volatile("ldmatrix.sync.aligned.m8n8.x4.shared.b16 {%0,%1,%2,%3}, [%4];"
                 : "=r"(r[0]), "=r"(r[1]), "=r"(r[2]), "=r"(r[3]) : "r"(addr));
}

__device__ __forceinline__ void ldsm4t(uint32_t* r, uint32_t addr) {
    asm volatile("ldmatrix.sync.aligned.m8n8.x4.trans.shared.b16 {%0,%1,%2,%3}, [%4];"
                 : "=r"(r[0]), "=r"(r[1]), "=r"(r[2]), "=r"(r[3]) : "r"(addr));
}

__device__ __forceinline__ void cpa16(uint32_t smem, const void* gptr) {
    asm volatile("cp.async.cg.shared.global [%0], [%1], 16;\n"
                 :: "r"(smem), "l"(gptr));
}
__device__ __forceinline__ void cp_commit() {
    asm volatile("cp.async.commit_group;\n" ::: "memory");
}
__device__ __forceinline__ void cp_wait0() {
    asm volatile("cp.async.wait_group 0;\n" ::: "memory");
}

__device__ __forceinline__ uint32_t s2u(const void* p) {
    return (uint32_t)__cvta_generic_to_shared(p);
}

// ---------------- prep: split weights + pre-gather bias ----------------------
__global__ void prep_kernel(const float* __restrict__ qkv_w,
                            const float* __restrict__ proj_w,
                            const float* __restrict__ bias_table,
                            const int*   __restrict__ rel_idx) {
    const int n1 = NQKV * DIMC, n2 = DIMC * DIMC, n3 = NHD * NTOK * NTOK;
    for (int i = blockIdx.x * blockDim.x + threadIdx.x; i < n1 + n2 + n3;
         i += gridDim.x * blockDim.x) {
        if (i < n1) {
            int n = i / DIMC, k = i % DIMC;
            float w = qkv_w[k * NQKV + n];
            __nv_bfloat16 h = __float2bfloat16(w);
            g_wqkvT_h[i] = h;
            g_wqkvT_l[i] = __float2bfloat16(w - __bfloat162float(h));
        } else if (i < n1 + n2) {
            int j = i - n1;
            int n = j / DIMC, k = j % DIMC;
            float w = proj_w[k * DIMC + n];
            __nv_bfloat16 h = __float2bfloat16(w);
            g_wprojT_h[j] = h;
            g_wprojT_l[j] = __float2bfloat16(w - __bfloat162float(h));
        } else {
            int j = i - n1 - n2;
            int h6 = j / (NTOK * NTOK);
            int rc = j % (NTOK * NTOK);
            g_bias6[h6 * BIAS_STRIDE + rc] = bias_table[rel_idx[rc] * NHD + h6];
        }
    }
}

// ---------------- GEMM: C[64-row tile, Nc] = A[64,192] * W^T + bias ----------
// A (hi/lo bf16) resident; B in 64-col chunks, hi/lo, single buffer.
// 4 warps = 2(M) x 2(N); warp tile 32M x 32N.
// Inner loop manually software-pipelined: fragments for kk+1 are loaded
// (double-buffered registers) before the 24 MMAs of kk issue.
#define GBM   64
#define GSTR  200                        // smem row stride in halves
#define SM_A  (GBM * GSTR)               // 12800 halves per A buffer
#define SM_B  (64 * GSTR)                // 12800 halves per B buffer
#define GEMM_SMEM ((2 * SM_A + 2 * SM_B) * 2)   // 102400 bytes

__global__ __launch_bounds__(128, 2)
void gemm_kernel(const float* __restrict__ Ax, float* __restrict__ Cout,
                 const float* __restrict__ bias, int nChunks, int mode) {
    extern __shared__ __nv_bfloat16 smb[];
    __nv_bfloat16* Ah = smb;
    __nv_bfloat16* Al = smb + SM_A;
    __nv_bfloat16* Bh = smb + 2 * SM_A;
    __nv_bfloat16* Bl = Bh + SM_B;

    const __nv_bfloat16* Bgh = mode ? g_wprojT_h : g_wqkvT_h;
    const __nv_bfloat16* Bgl = mode ? g_wprojT_l : g_wqkvT_l;

    const int tid = threadIdx.x;
    const size_t rbase = (size_t)blockIdx.x * GBM;

    // B chunk 0 (async)
    for (int i = tid; i < 64 * 24; i += 128) {
        int row = i / 24, j = i % 24;
        const size_t go = (size_t)row * DIMC + j * 8;
        cpa16(s2u(Bh + row * GSTR + j * 8), Bgh + go);
        cpa16(s2u(Bl + row * GSTR + j * 8), Bgl + go);
    }
    cp_commit();

    if (mode == 0) {
        // A: fp32 x, convert+split into smem
        for (int i = tid; i < GBM * 48; i += 128) {
            int row = i / 48, j = i % 48;
            float4 v = *(const float4*)(Ax + (rbase + row) * DIMC + j * 4);
            __nv_bfloat16 h0 = __float2bfloat16(v.x), h1 = __float2bfloat16(v.y);
            __nv_bfloat16 h2 = __float2bfloat16(v.z), h3 = __float2bfloat16(v.w);
            __nv_bfloat16 l0 = __float2bfloat16(v.x - __bfloat162float(h0));
            __nv_bfloat16 l1 = __float2bfloat16(v.y - __bfloat162float(h1));
            __nv_bfloat16 l2 = __float2bfloat16(v.z - __bfloat162float(h2));
            __nv_bfloat16 l3 = __float2bfloat16(v.w - __bfloat162float(h3));
            *(uint2*)(Ah + row * GSTR + j * 4) = make_uint2(packbf(h0, h1), packbf(h2, h3));
            *(uint2*)(Al + row * GSTR + j * 4) = make_uint2(packbf(l0, l1), packbf(l2, l3));
        }
    } else {
        for (int i = tid; i < GBM * 24; i += 128) {
            int row = i / 24, j = i % 24;
            const size_t go = (rbase + row) * DIMC + j * 8;
            cpa16(s2u(Ah + row * GSTR + j * 8), g_aoh + go);
            cpa16(s2u(Al + row * GSTR + j * 8), g_aol + go);
        }
        cp_commit();
    }
    cp_wait0();
    __syncthreads();

    const int lane = tid & 31, warp = tid >> 5;
    const int g = lane >> 2, tg = lane & 3;
    const int m0 = (warp >> 1) * 32;        // 2 warps over M=64
    const int n0 = (warp & 1) * 32;         // 2 warps over 64-col chunk

    const int aRow = m0 + (lane & 15);
    const int aK   = (lane >> 4) * 8;
    const int b4Row = n0 + (lane & 7) + ((lane >> 4) << 3);
    const int bK    = ((lane >> 3) & 1) * 8;

    const uint32_t aBaseH = s2u(Ah + aRow * GSTR + aK);
    const uint32_t aBaseL = aBaseH + SM_A * 2;
    const uint32_t bBaseH = s2u(Bh + b4Row * GSTR + bK);
    const uint32_t bBaseL = bBaseH + SM_B * 2;
    const uint32_t ROW16 = 16 * GSTR * 2;   // +16 rows in bytes

    for (int c = 0; c < nChunks; c++) {
        float acc[2][4][4];
#pragma unroll
        for (int mt = 0; mt < 2; mt++)
#pragma unroll
            for (int nt = 0; nt < 4; nt++)
#pragma unroll
                for (int r = 0; r < 4; r++) acc[mt][nt][r] = 0.f;

        // double-buffered fragment registers; load kk=0 into slot 0
        uint32_t fah[2][8], fal[2][8], fbh[2][8], fbl[2][8];
        ldsm4(fah[0],     aBaseH);
        ldsm4(fah[0] + 4, aBaseH + ROW16);
        ldsm4(fbh[0],     bBaseH);
        ldsm4(fbh[0] + 4, bBaseH + ROW16);
        ldsm4(fal[0],     aBaseL);
        ldsm4(fal[0] + 4, aBaseL + ROW16);
        ldsm4(fbl[0],     bBaseL);
        ldsm4(fbl[0] + 4, bBaseL + ROW16);

#pragma unroll
        for (int kk = 0; kk < 12; kk++) {
            const int cur = kk & 1, nxt = cur ^ 1;
            if (kk + 1 < 12) {              // prefetch kk+1 fragments
                const uint32_t o = (uint32_t)(kk + 1) * 32;
                ldsm4(fah[nxt],     aBaseH + o);
                ldsm4(fah[nxt] + 4, aBaseH + ROW16 + o);
                ldsm4(fbh[nxt],     bBaseH + o);
                ldsm4(fbh[nxt] + 4, bBaseH + ROW16 + o);
                ldsm4(fal[nxt],     aBaseL + o);
                ldsm4(fal[nxt] + 4, aBaseL + ROW16 + o);
                ldsm4(fbl[nxt],     bBaseL + o);
                ldsm4(fbl[nxt] + 4, bBaseL + ROW16 + o);
            }
#pragma unroll
            for (int mt = 0; mt < 2; mt++)
#pragma unroll
                for (int nt = 0; nt < 4; nt++) {
                    mma16816(acc[mt][nt], fah[cur] + 4 * mt,
                             fbh[cur][2 * nt], fbh[cur][2 * nt + 1]);
                    mma16816(acc[mt][nt], fal[cur] + 4 * mt,
                             fbh[cur][2 * nt], fbh[cur][2 * nt + 1]);
                    mma16816(acc[mt][nt], fah[cur] + 4 * mt,
                             fbl[cur][2 * nt], fbl[cur][2 * nt + 1]);
                }
        }
        __syncthreads();                    // all warps done reading B chunk c

        if (c + 1 < nChunks) {              // overwrite B with next chunk
            for (int i = tid; i < 64 * 24; i += 128) {
                int row = i / 24, j = i % 24;
                const size_t go = (size_t)((c + 1) * 64 + row) * DIMC + j * 8;
                cpa16(s2u(Bh + row * GSTR + j * 8), Bgh + go);
                cpa16(s2u(Bl + row * GSTR + j * 8), Bgl + go);
            }
            cp_commit();
        }

        // epilogue for chunk c (overlaps in-flight cp.async)
        if (mode == 0) {
            const int which = c / 3;
            const int hb = (c % 3) * 2;
#pragma unroll
            for (int mt = 0; mt < 2; mt++)
#pragma unroll
                for (int rr = 0; rr < 2; rr++) {
                    size_t r = rbase + m0 + mt * 16 + g + rr * 8;
                    unsigned bwin = (unsigned)(r / NTOK), tok = (unsigned)(r % NTOK);
                    size_t ob = ((size_t)(bwin * 3 + which) * NHD) * NTOK * HDIM
                                + (size_t)tok * HDIM;
#pragma unroll
                    for (int nt = 0; nt < 4; nt++) {
                        int local = n0 + nt * 8 + tg * 2;
                        int hh = hb + (local >> 5), d = local & 31;
                        float v0 = acc[mt][nt][rr * 2 + 0] + bias[c * 64 + local];
                        float v1 = acc[mt][nt][rr * 2 + 1] + bias[c * 64 + local + 1];
                        __nv_bfloat16 h0 = __float2bfloat16(v0);
                        __nv_bfloat16 h1 = __float2bfloat16(v1);
                        size_t off = ob + (size_t)hh * NTOK * HDIM + d;
                        *(uint32_t*)(g_qkvh + off) = packbf(h0, h1);
                        *(uint32_t*)(g_qkvl + off) =
                            packbf(__float2bfloat16(v0 - __bfloat162float(h0)),
                                   __float2bfloat16(v1 - __bfloat162float(h1)));
                    }
                }
        } else {
#pragma unroll
            for (int mt = 0; mt < 2; mt++)
#pragma unroll
                for (int rr = 0; rr < 2; rr++) {
                    size_t r = rbase + m0 + mt * 16 + g + rr * 8;
#pragma unroll
                    for (int nt = 0; nt < 4; nt++) {
                        int col = c * 64 + n0 + nt * 8 + tg * 2;
                        *(float2*)(Cout + r * DIMC + col) =
                            make_float2(acc[mt][nt][rr * 2 + 0] + bias[col],
                                        acc[mt][nt][rr * 2 + 1] + bias[col + 1]);
                    }
                }
        }

        if (c + 1 < nChunks) {
            cp_wait0();
            __syncthreads();
        }
    }
}

// ---------------- attention: one CTA per (2 windows, head) -------------------
#define ABUF 1960                 // halves per buffer
#define AB_B 3920                 // bytes per buffer
#define ATTN_SMEM (12 * AB_B + BIAS_STRIDE * 4)   // 56656 bytes

__global__ __launch_bounds__(256)
void attn_kernel() {
    extern __shared__ char dsm[];
    __nv_bfloat16* sQKV = (__nv_bfloat16*)dsm;
    float* sBias = (float*)(dsm + 12 * AB_B);

    const int b = blockIdx.x, h = blockIdx.y;   // b = window pair
    const int tid = threadIdx.x;
    const uint32_t sBase = s2u(sQKV);
    const uint32_t sBiasU = s2u(sBias);

    {
        const size_t slabStride = (size_t)NTOK * HDIM;               // 1568
        const float* biasg = g_bias6 + h * BIAS_STRIDE;
        for (int i = tid; i < 12 * 196 + 601; i += 256) {
            if (i < 12 * 196) {
                int s = i / 196, j = i - s * 196;
                int wi = s / 6, sb2 = s - wi * 6;
                int which = sb2 >> 1;
                const size_t base =
                    ((size_t)(b * 2 + wi) * 3 * NHD + h) * slabStride
                    + (size_t)which * NHD * slabStride;
                const __nv_bfloat16* src =
                    ((sb2 & 1) ? g_qkvl : g_qkvh) + base + j * 8;
                cpa16(sBase + s * AB_B + (j >> 2) * 80 + (j & 3) * 16, src);
            } else {
                int j = i - 12 * 196;
                cpa16(sBiasU + j * 16, biasg + j * 4);
            }
        }
        cp_commit();
    }

    const int lane = tid & 31, w = tid >> 5;
    const int wi = w >> 2, wl = w & 3;
    const int g = lane >> 2, tg = lane & 3;
    const uint32_t qkvB = sBase + wi * (6 * AB_B);

    const int qRow = wl * 16 + (lane & 15);
    const uint32_t qOff = (uint32_t)(min(qRow, 48) * 80 + (lane >> 4) * 16);
    const int kR = (lane & 7) + ((lane >> 4) << 3);
    const int kC = ((lane >> 3) & 1) * 16;
    const int vR0 = (lane & 7) + (((lane >> 3) & 1) << 3);
    const int vC = (lane >> 4) * 16;

    cp_wait0();
    __syncthreads();

    float s[8][4];
#pragma unroll
    for (int nt = 0; nt < 8; nt++)
#pragma unroll
        for (int r = 0; r < 4; r++) s[nt][r] = 0.f;

#pragma unroll
    for (int part = 0; part < 3; part++) {
        const uint32_t qB = qkvB + ((part == 1) ? AB_B : 0) + qOff;
        const uint32_t kB = qkvB + 2 * AB_B + ((part == 2) ? AB_B : 0);
#pragma unroll
        for (int kk = 0; kk < 2; kk++) {
            uint32_t a[4];
            ldsm4(a, qB + kk * 32);
#pragma unroll
            for (int p = 0; p < 4; p++) {
                uint32_t bfr[4];
                ldsm4(bfr, kB + (uint32_t)(min(p * 16 + kR, 48) * 80 + kC) + kk * 32);
                mma16816(s[2 * p], a, bfr[0], bfr[1]);
                mma16816(s[2 * p + 1], a, bfr[2], bfr[3]);
            }
        }
    }

    const int r0 = wl * 16 + g, r1 = r0 + 8;
#pragma unroll
    for (int nt = 0; nt < 8; nt++) {
#pragma unroll
        for (int j = 0; j < 2; j++) {
            int col = nt * 8 + tg * 2 + j;
            if (col < NTOK) {
                s[nt][j]     = s[nt][j]     * SCALEA + (r0 < NTOK ? sBias[r0 * NTOK + col] : 0.f);
                s[nt][2 + j] = s[nt][2 + j] * SCALEA + (r1 < NTOK ? sBias[r1 * NTOK + col] : 0.f);
            } else {
                s[nt][j] = -1e30f;
                s[nt][2 + j] = -1e30f;
            }
        }
    }

    float m0 = -1e30f, m1 = -1e30f;
#pragma unroll
    for (int nt = 0; nt < 8; nt++) {
        m0 = fmaxf(m0, fmaxf(s[nt][0], s[nt][1]));
        m1 = fmaxf(m1, fmaxf(s[nt][2], s[nt][3]));
    }
    m0 = fmaxf(m0, __shfl_xor_sync(0xffffffffu, m0, 1));
    m0 = fmaxf(m0, __shfl_xor_sync(0xffffffffu, m0, 2));
    m1 = fmaxf(m1, __shfl_xor_sync(0xffffffffu, m1, 1));
    m1 = fmaxf(m1, __shfl_xor_sync(0xffffffffu, m1, 2));
    float d0 = 0.f, d1 = 0.f;
#pragma unroll
    for (int nt = 0; nt < 8; nt++) {
        s[nt][0] = __expf(s[nt][0] - m0); d0 += s[nt][0];
        s[nt][1] = __expf(s[nt][1] - m0); d0 += s[nt][1];
        s[nt][2] = __expf(s[nt][2] - m1); d1 += s[nt][2];
        s[nt][3] = __expf(s[nt][3] - m1); d1 += s[nt][3];
    }
    d0 += __shfl_xor_sync(0xffffffffu, d0, 1);
    d0 += __shfl_xor_sync(0xffffffffu, d0, 2);
    d1 += __shfl_xor_sync(0xffffffffu, d1, 1);
    d1 += __shfl_xor_sync(0xffffffffu, d1, 2);
    const float inv0 = 1.f / d0, inv1 = 1.f / d1;

    uint32_t aPh[4][4], aPl[4][4];
#pragma unroll
    for (int kc = 0; kc < 4; kc++) {
#pragma unroll
        for (int t2 = 0; t2 < 2; t2++) {
            int tile = 2 * kc + t2;
            float p0 = s[tile][0] * inv0, p1 = s[tile][1] * inv0;
            float p2 = s[tile][2] * inv1, p3 = s[tile][3] * inv1;
            __nv_bfloat16 h0 = __float2bfloat16(p0), h1 = __float2bfloat16(p1);
            __nv_bfloat16 h2 = __float2bfloat16(p2), h3 = __float2bfloat16(p3);
            aPh[kc][t2]     = packbf(h0, h1);
            aPh[kc][t2 + 2] = packbf(h2, h3);
            aPl[kc][t2]     = packbf(__float2bfloat16(p0 - __bfloat162float(h0)),
                                     __float2bfloat16(p1 - __bfloat162float(h1)));
            aPl[kc][t2 + 2] = packbf(__float2bfloat16(p2 - __bfloat162float(h2)),
                                     __float2bfloat16(p3 - __bfloat162float(h3)));
        }
    }
#pragma unroll
    for (int kc = 0; kc < 4; kc++) {
        uint32_t t = aPh[kc][1]; aPh[kc][1] = aPh[kc][2]; aPh[kc][2] = t;
        t = aPl[kc][1]; aPl[kc][1] = aPl[kc][2]; aPl[kc][2] = t;
    }

    float o[4][4];
#pragma unroll
    for (int nt = 0; nt < 4; nt++)
#pragma unroll
        for (int r = 0; r < 4; r++) o[nt][r] = 0.f;

#pragma unroll
    for (int part = 0; part < 3; part++) {
        const uint32_t (*Ap)[4] = (part == 1) ? aPl : aPh;
        const uint32_t vB = qkvB + 4 * AB_B + ((part == 2) ? AB_B : 0);
#pragma unroll
        for (int kc = 0; kc < 4; kc++) {
            const uint32_t rowOff = (uint32_t)(min(vR0 + kc * 16, 48) * 80 + vC);
#pragma unroll
            for (int dh = 0; dh < 2; dh++) {
                uint32_t bv[4];
                ldsm4t(bv, vB + rowOff + dh * 32);
                mma16816(o[dh * 2 + 0], Ap[kc], bv[0], bv[1]);
                mma16816(o[dh * 2 + 1], Ap[kc], bv[2], bv[3]);
            }
        }
    }

    const size_t bw = (size_t)(b * 2 + wi);
#pragma unroll
    for (int nt = 0; nt < 4; nt++) {
        int d = h * HDIM + nt * 8 + tg * 2;
        if (r0 < NTOK) {
            size_t off = (bw * NTOK + r0) * DIMC + d;
            __nv_bfloat16 h0 = __float2bfloat16(o[nt][0]);
            __nv_bfloat16 h1 = __float2bfloat16(o[nt][1]);
            *(uint32_t*)(g_aoh + off) = packbf(h0, h1);
            *(uint32_t*)(g_aol + off) =
                packbf(__float2bfloat16(o[nt][0] - __bfloat162float(h0)),
                       __float2bfloat16(o[nt][1] - __bfloat162float(h1)));
        }
        if (r1 < NTOK) {
            size_t off = (bw * NTOK + r1) * DIMC + d;
            __nv_bfloat16 h2 = __float2bfloat16(o[nt][2]);
            __nv_bfloat16 h3 = __float2bfloat16(o[nt][3]);
            *(uint32_t*)(g_aoh + off) = packbf(h2, h3);
            *(uint32_t*)(g_aol + off) =
                packbf(__float2bfloat16(o[nt][2] - __bfloat162float(h2)),
                       __float2bfloat16(o[nt][3] - __bfloat162float(h3)));
        }
    }
}

// ---------------- launch ------------------------------------------------------
extern "C" void kernel_launch(void* const* d_in, const int* in_sizes, int n_in,
                              void* d_out, int out_size) {
    const float* x          = (const float*)d_in[0];
    const float* qkv_w      = (const float*)d_in[1];
    const float* qkv_b      = (const float*)d_in[2];
    const float* proj_w     = (const float*)d_in[3];
    const float* proj_b     = (const float*)d_in[4];
    const float* bias_table = (const float*)d_in[5];
    const int*   rel_idx    = (const int*)d_in[6];
    float* out = (float*)d_out;

    static bool attr_set = false;
    if (!attr_set) {
        cudaFuncSetAttribute(gemm_kernel, cudaFuncAttributeMaxDynamicSharedMemorySize,
                             GEMM_SMEM);
        cudaFuncSetAttribute(attn_kernel, cudaFuncAttributeMaxDynamicSharedMemorySize,
                             ATTN_SMEM);
        attr_set = true;
    }

    prep_kernel<<<640, 256>>>(qkv_w, proj_w, bias_table, rel_idx);

    gemm_kernel<<<T_TOK / GBM, 128, GEMM_SMEM>>>(x, nullptr, qkv_b, 9, 0);

    dim3 g2(2048, NHD);
    attn_kernel<<<g2, 256, ATTN_SMEM>>>();

    gemm_kernel<<<T_TOK / GBM, 128, GEMM_SMEM>>>(nullptr, out, proj_b, 3, 1);
}

// round 15
// speedup vs baseline: 1.4879x; 1.0054x over previous
#include <cuda_runtime.h>
#include <cuda_bf16.h>
#include <cstdint>
#include <cstddef>

#define T_TOK 200704          // 4096 * 49 tokens
#define DIMC  192
#define NHD   6
#define HDIM  32
#define NTOK  49
#define NQKV  576
#define SCALEA 0.17677669529663687f
#define BIAS_STRIDE 2404      // 49*49 padded to 16B multiple (floats)

// ---------------- device scratch (static; no runtime allocation) -------------
__device__ __nv_bfloat16 g_qkvh[(size_t)T_TOK * NQKV];   // [b][which][h][tok][d]
__device__ __nv_bfloat16 g_qkvl[(size_t)T_TOK * NQKV];
__device__ __nv_bfloat16 g_aoh[(size_t)T_TOK * DIMC];    // attn out hi [t][c]
__device__ __nv_bfloat16 g_aol[(size_t)T_TOK * DIMC];
__device__ __nv_bfloat16 g_wqkvT_h[NQKV * DIMC];
__device__ __nv_bfloat16 g_wqkvT_l[NQKV * DIMC];
__device__ __nv_bfloat16 g_wprojT_h[DIMC * DIMC];
__device__ __nv_bfloat16 g_wprojT_l[DIMC * DIMC];
__device__ float g_bias6[NHD * BIAS_STRIDE];

// ---------------- helpers ----------------------------------------------------
__device__ __forceinline__ uint32_t packbf(__nv_bfloat16 a, __nv_bfloat16 b) {
    __nv_bfloat162 t(a, b);
    return *reinterpret_cast<uint32_t*>(&t);
}

__device__ __forceinline__ void mma16816(float* c, const uint32_t* a,
                                         uint32_t b0, uint32_t b1) {
    asm volatile(
        "mma.sync.aligned.m16n8k16.row.col.f32.bf16.bf16.f32 "
        "{%0,%1,%2,%3},{%4,%5,%6,%7},{%8,%9},{%0,%1,%2,%3};"
        : "+f"(c[0]), "+f"(c[1]), "+f"(c[2]), "+f"(c[3])
        : "r"(a[0]), "r"(a[1]), "r"(a[2]), "r"(a[3]), "r"(b0), "r"(b1));
}

__device__ __forceinline__ void ldsm4(uint32_t* r, uint32_t addr) {
    asm volatile("ldmatrix.sync.aligned.m8n8.x4.shared.b16 {%0,%1,%2,%3}, [%4];"
                 : "=r"(r[0]), "=r"(r[1]), "=r"(r[2]), "=r"(r[3]) : "r"(addr));
}

__device__ __forceinline__ void ldsm4t(uint32_t* r, uint32_t addr) {
    asm volatile("ldmatrix.sync.aligned.m8n8.x4.trans.shared.b16 {%0,%1,%2,%3}, [%4];"
                 : "=r"(r[0]), "=r"(r[1]), "=r"(r[2]), "=r"(r[3]) : "r"(addr));
}

__device__ __forceinline__ void cpa16(uint32_t smem, const void* gptr) {
    asm volatile("cp.async.cg.shared.global [%0], [%1], 16;\n"
                 :: "r"(smem), "l"(gptr));
}
__device__ __forceinline__ void cp_commit() {
    asm volatile("cp.async.commit_group;\n" ::: "memory");
}
__device__ __forceinline__ void cp_wait0() {
    asm volatile("cp.async.wait_group 0;\n" ::: "memory");
}

__device__ __forceinline__ uint32_t s2u(const void* p) {
    return (uint32_t)__cvta_generic_to_shared(p);
}

// ---------------- prep: split weights + pre-gather bias ----------------------
__global__ void prep_kernel(const float* __restrict__ qkv_w,
                            const float* __restrict__ proj_w,
                            const float* __restrict__ bias_table,
                            const int*   __restrict__ rel_idx) {
    const int n1 = NQKV * DIMC, n2 = DIMC * DIMC, n3 = NHD * NTOK * NTOK;
    for (int i = blockIdx.x * blockDim.x + threadIdx.x; i < n1 + n2 + n3;
         i += gridDim.x * blockDim.x) {
        if (i < n1) {
            int n = i / DIMC, k = i % DIMC;
            float w = qkv_w[k * NQKV + n];
            __nv_bfloat16 h = __float2bfloat16(w);
            g_wqkvT_h[i] = h;
            g_wqkvT_l[i] = __float2bfloat16(w - __bfloat162float(h));
        } else if (i < n1 + n2) {
            int j = i - n1;
            int n = j / DIMC, k = j % DIMC;
            float w = proj_w[k * DIMC + n];
            __nv_bfloat16 h = __float2bfloat16(w);
            g_wprojT_h[j] = h;
            g_wprojT_l[j] = __float2bfloat16(w - __bfloat162float(h));
        } else {
            int j = i - n1 - n2;
            int h6 = j / (NTOK * NTOK);
            int rc = j % (NTOK * NTOK);
            g_bias6[h6 * BIAS_STRIDE + rc] = bias_table[rel_idx[rc] * NHD + h6];
        }
    }
}

// ---------------- GEMM: C[64-row tile, Nc] = A[64,192] * W^T + bias ----------
// A (hi/lo bf16) resident; B in 64-col chunks, hi/lo, single buffer.
// 4 warps = 2(M) x 2(N); warp tile 32M x 32N.
// MMAs issued part-major within each kk: 8 independent accumulators between
// successive touches of the same accumulator (no RAW stall chains).
#define GBM   64
#define GSTR  200                        // smem row stride in halves
#define SM_A  (GBM * GSTR)               // 12800 halves per A buffer
#define SM_B  (64 * GSTR)                // 12800 halves per B buffer
#define GEMM_SMEM ((2 * SM_A + 2 * SM_B) * 2)   // 102400 bytes

__global__ __launch_bounds__(128, 2)
void gemm_kernel(const float* __restrict__ Ax, float* __restrict__ Cout,
                 const float* __restrict__ bias, int nChunks, int mode) {
    extern __shared__ __nv_bfloat16 smb[];
    __nv_bfloat16* Ah = smb;
    __nv_bfloat16* Al = smb + SM_A;
    __nv_bfloat16* Bh = smb + 2 * SM_A;
    __nv_bfloat16* Bl = Bh + SM_B;

    const __nv_bfloat16* Bgh = mode ? g_wprojT_h : g_wqkvT_h;
    const __nv_bfloat16* Bgl = mode ? g_wprojT_l : g_wqkvT_l;

    const int tid = threadIdx.x;
    const size_t rbase = (size_t)blockIdx.x * GBM;

    // B chunk 0 (async)
    for (int i = tid; i < 64 * 24; i += 128) {
        int row = i / 24, j = i % 24;
        const size_t go = (size_t)row * DIMC + j * 8;
        cpa16(s2u(Bh + row * GSTR + j * 8), Bgh + go);
        cpa16(s2u(Bl + row * GSTR + j * 8), Bgl + go);
    }
    cp_commit();

    if (mode == 0) {
        // A: fp32 x, convert+split into smem
        for (int i = tid; i < GBM * 48; i += 128) {
            int row = i / 48, j = i % 48;
            float4 v = *(const float4*)(Ax + (rbase + row) * DIMC + j * 4);
            __nv_bfloat16 h0 = __float2bfloat16(v.x), h1 = __float2bfloat16(v.y);
            __nv_bfloat16 h2 = __float2bfloat16(v.z), h3 = __float2bfloat16(v.w);
            __nv_bfloat16 l0 = __float2bfloat16(v.x - __bfloat162float(h0));
            __nv_bfloat16 l1 = __float2bfloat16(v.y - __bfloat162float(h1));
            __nv_bfloat16 l2 = __float2bfloat16(v.z - __bfloat162float(h2));
            __nv_bfloat16 l3 = __float2bfloat16(v.w - __bfloat162float(h3));
            *(uint2*)(Ah + row * GSTR + j * 4) = make_uint2(packbf(h0, h1), packbf(h2, h3));
            *(uint2*)(Al + row * GSTR + j * 4) = make_uint2(packbf(l0, l1), packbf(l2, l3));
        }
    } else {
        for (int i = tid; i < GBM * 24; i += 128) {
            int row = i / 24, j = i % 24;
            const size_t go = (rbase + row) * DIMC + j * 8;
            cpa16(s2u(Ah + row * GSTR + j * 8), g_aoh + go);
            cpa16(s2u(Al + row * GSTR + j * 8), g_aol + go);
        }
        cp_commit();
    }
    cp_wait0();
    __syncthreads();

    const int lane = tid & 31, warp = tid >> 5;
    const int g = lane >> 2, tg = lane & 3;
    const int m0 = (warp >> 1) * 32;        // 2 warps over M=64
    const int n0 = (warp & 1) * 32;         // 2 warps over 64-col chunk

    const int aRow = m0 + (lane & 15);
    const int aK   = (lane >> 4) * 8;
    const int b4Row = n0 + (lane & 7) + ((lane >> 4) << 3);
    const int bK    = ((lane >> 3) & 1) * 8;

    const uint32_t aBaseH = s2u(Ah + aRow * GSTR + aK);
    const uint32_t aBaseL = aBaseH + SM_A * 2;
    const uint32_t bBaseH = s2u(Bh + b4Row * GSTR + bK);
    const uint32_t bBaseL = bBaseH + SM_B * 2;
    const uint32_t ROW16 = 16 * GSTR * 2;   // +16 rows in bytes

    for (int c = 0; c < nChunks; c++) {
        float acc[2][4][4];
#pragma unroll
        for (int mt = 0; mt < 2; mt++)
#pragma unroll
            for (int nt = 0; nt < 4; nt++)
#pragma unroll
                for (int r = 0; r < 4; r++) acc[mt][nt][r] = 0.f;

#pragma unroll
        for (int kk = 0; kk < 12; kk++) {
            uint32_t ah[8], al[8], bh[8], bl[8];
            // part-0 operands first; al/bl load latency hides behind part-0 MMAs
            ldsm4(ah,     aBaseH + kk * 32);
            ldsm4(ah + 4, aBaseH + ROW16 + kk * 32);
            ldsm4(bh,     bBaseH + kk * 32);
            ldsm4(bh + 4, bBaseH + ROW16 + kk * 32);
            ldsm4(al,     aBaseL + kk * 32);
            ldsm4(al + 4, aBaseL + ROW16 + kk * 32);
            ldsm4(bl,     bBaseL + kk * 32);
            ldsm4(bl + 4, bBaseL + ROW16 + kk * 32);
            // part-major: 8 independent accumulators between reuses
#pragma unroll
            for (int mt = 0; mt < 2; mt++)
#pragma unroll
                for (int nt = 0; nt < 4; nt++)
                    mma16816(acc[mt][nt], ah + 4 * mt, bh[2 * nt], bh[2 * nt + 1]);
#pragma unroll
            for (int mt = 0; mt < 2; mt++)
#pragma unroll
                for (int nt = 0; nt < 4; nt++)
                    mma16816(acc[mt][nt], al + 4 * mt, bh[2 * nt], bh[2 * nt + 1]);
#pragma unroll
            for (int mt = 0; mt < 2; mt++)
#pragma unroll
                for (int nt = 0; nt < 4; nt++)
                    mma16816(acc[mt][nt], ah + 4 * mt, bl[2 * nt], bl[2 * nt + 1]);
        }
        __syncthreads();                    // all warps done reading B chunk c

        if (c + 1 < nChunks) {              // overwrite B with next chunk
            for (int i = tid; i < 64 * 24; i += 128) {
                int row = i / 24, j = i % 24;
                const size_t go = (size_t)((c + 1) * 64 + row) * DIMC + j * 8;
                cpa16(s2u(Bh + row * GSTR + j * 8), Bgh + go);
                cpa16(s2u(Bl + row * GSTR + j * 8), Bgl + go);
            }
            cp_commit();
        }

        // epilogue for chunk c (overlaps in-flight cp.async)
        if (mode == 0) {
            const int which = c / 3;
            const int hb = (c % 3) * 2;
#pragma unroll
            for (int mt = 0; mt < 2; mt++)
#pragma unroll
                for (int rr = 0; rr < 2; rr++) {
                    size_t r = rbase + m0 + mt * 16 + g + rr * 8;
                    unsigned bwin = (unsigned)(r / NTOK), tok = (unsigned)(r % NTOK);
                    size_t ob = ((size_t)(bwin * 3 + which) * NHD) * NTOK * HDIM
                                + (size_t)tok * HDIM;
#pragma unroll
                    for (int nt = 0; nt < 4; nt++) {
                        int local = n0 + nt * 8 + tg * 2;
                        int hh = hb + (local >> 5), d = local & 31;
                        float v0 = acc[mt][nt][rr * 2 + 0] + bias[c * 64 + local];
                        float v1 = acc[mt][nt][rr * 2 + 1] + bias[c * 64 + local + 1];
                        __nv_bfloat16 h0 = __float2bfloat16(v0);
                        __nv_bfloat16 h1 = __float2bfloat16(v1);
                        size_t off = ob + (size_t)hh * NTOK * HDIM + d;
                        *(uint32_t*)(g_qkvh + off) = packbf(h0, h1);
                        *(uint32_t*)(g_qkvl + off) =
                            packbf(__float2bfloat16(v0 - __bfloat162float(h0)),
                                   __float2bfloat16(v1 - __bfloat162float(h1)));
                    }
                }
        } else {
#pragma unroll
            for (int mt = 0; mt < 2; mt++)
#pragma unroll
                for (int rr = 0; rr < 2; rr++) {
                    size_t r = rbase + m0 + mt * 16 + g + rr * 8;
#pragma unroll
                    for (int nt = 0; nt < 4; nt++) {
                        int col = c * 64 + n0 + nt * 8 + tg * 2;
                        *(float2*)(Cout + r * DIMC + col) =
                            make_float2(acc[mt][nt][rr * 2 + 0] + bias[col],
                                        acc[mt][nt][rr * 2 + 1] + bias[col + 1]);
                    }
                }
        }

        if (c + 1 < nChunks) {
            cp_wait0();
            __syncthreads();
        }
    }
}

// ---------------- attention: one CTA per (2 windows, head) -------------------
#define ABUF 1960                 // halves per buffer
#define AB_B 3920                 // bytes per buffer
#define ATTN_SMEM (12 * AB_B + BIAS_STRIDE * 4)   // 56656 bytes

__global__ __launch_bounds__(256)
void attn_kernel() {
    extern __shared__ char dsm[];
    __nv_bfloat16* sQKV = (__nv_bfloat16*)dsm;
    float* sBias = (float*)(dsm + 12 * AB_B);

    const int b = blockIdx.x, h = blockIdx.y;   // b = window pair
    const int tid = threadIdx.x;
    const uint32_t sBase = s2u(sQKV);
    const uint32_t sBiasU = s2u(sBias);

    {
        const size_t slabStride = (size_t)NTOK * HDIM;               // 1568
        const float* biasg = g_bias6 + h * BIAS_STRIDE;
        for (int i = tid; i < 12 * 196 + 601; i += 256) {
            if (i < 12 * 196) {
                int s = i / 196, j = i - s * 196;
                int wi = s / 6, sb2 = s - wi * 6;
                int which = sb2 >> 1;
                const size_t base =
                    ((size_t)(b * 2 + wi) * 3 * NHD + h) * slabStride
                    + (size_t)which * NHD * slabStride;
                const __nv_bfloat16* src =
                    ((sb2 & 1) ? g_qkvl : g_qkvh) + base + j * 8;
                cpa16(sBase + s * AB_B + (j >> 2) * 80 + (j & 3) * 16, src);
            } else {
                int j = i - 12 * 196;
                cpa16(sBiasU + j * 16, biasg + j * 4);
            }
        }
        cp_commit();
    }

    const int lane = tid & 31, w = tid >> 5;
    const int wi = w >> 2, wl = w & 3;
    const int g = lane >> 2, tg = lane & 3;
    const uint32_t qkvB = sBase + wi * (6 * AB_B);

    const int qRow = wl * 16 + (lane & 15);
    const uint32_t qOff = (uint32_t)(min(qRow, 48) * 80 + (lane >> 4) * 16);
    const int kR = (lane & 7) + ((lane >> 4) << 3);
    const int kC = ((lane >> 3) & 1) * 16;
    const int vR0 = (lane & 7) + (((lane >> 3) & 1) << 3);
    const int vC = (lane >> 4) * 16;

    cp_wait0();
    __syncthreads();

    float s[8][4];
#pragma unroll
    for (int nt = 0; nt < 8; nt++)
#pragma unroll
        for (int r = 0; r < 4; r++) s[nt][r] = 0.f;

#pragma unroll
    for (int part = 0; part < 3; part++) {
        const uint32_t qB = qkvB + ((part == 1) ? AB_B : 0) + qOff;
        const uint32_t kB = qkvB + 2 * AB_B + ((part == 2) ? AB_B : 0);
#pragma unroll
        for (int kk = 0; kk < 2; kk++) {
            uint32_t a[4];
            ldsm4(a, qB + kk * 32);
#pragma unroll
            for (int p = 0; p < 4; p++) {
                uint32_t bfr[4];
                ldsm4(bfr, kB + (uint32_t)(min(p * 16 + kR, 48) * 80 + kC) + kk * 32);
                mma16816(s[2 * p], a, bfr[0], bfr[1]);
                mma16816(s[2 * p + 1], a, bfr[2], bfr[3]);
            }
        }
    }

    const int r0 = wl * 16 + g, r1 = r0 + 8;
#pragma unroll
    for (int nt = 0; nt < 8; nt++) {
#pragma unroll
        for (int j = 0; j < 2; j++) {
            int col = nt * 8 + tg * 2 + j;
            if (col < NTOK) {
                s[nt][j]     = s[nt][j]     * SCALEA + (r0 < NTOK ? sBias[r0 * NTOK + col] : 0.f);
                s[nt][2 + j] = s[nt][2 + j] * SCALEA + (r1 < NTOK ? sBias[r1 * NTOK + col] : 0.f);
            } else {
                s[nt][j] = -1e30f;
                s[nt][2 + j] = -1e30f;
            }
        }
    }

    float m0 = -1e30f, m1 = -1e30f;
#pragma unroll
    for (int nt = 0; nt < 8; nt++) {
        m0 = fmaxf(m0, fmaxf(s[nt][0], s[nt][1]));
        m1 = fmaxf(m1, fmaxf(s[nt][2], s[nt][3]));
    }
    m0 = fmaxf(m0, __shfl_xor_sync(0xffffffffu, m0, 1));
    m0 = fmaxf(m0, __shfl_xor_sync(0xffffffffu, m0, 2));
    m1 = fmaxf(m1, __shfl_xor_sync(0xffffffffu, m1, 1));
    m1 = fmaxf(m1, __shfl_xor_sync(0xffffffffu, m1, 2));
    float d0 = 0.f, d1 = 0.f;
#pragma unroll
    for (int nt = 0; nt < 8; nt++) {
        s[nt][0] = __expf(s[nt][0] - m0); d0 += s[nt][0];
        s[nt][1] = __expf(s[nt][1] - m0); d0 += s[nt][1];
        s[nt][2] = __expf(s[nt][2] - m1); d1 += s[nt][2];
        s[nt][3] = __expf(s[nt][3] - m1); d1 += s[nt][3];
    }
    d0 += __shfl_xor_sync(0xffffffffu, d0, 1);
    d0 += __shfl_xor_sync(0xffffffffu, d0, 2);
    d1 += __shfl_xor_sync(0xffffffffu, d1, 1);
    d1 += __shfl_xor_sync(0xffffffffu, d1, 2);
    const float inv0 = 1.f / d0, inv1 = 1.f / d1;

    uint32_t aPh[4][4], aPl[4][4];
#pragma unroll
    for (int kc = 0; kc < 4; kc++) {
#pragma unroll
        for (int t2 = 0; t2 < 2; t2++) {
            int tile = 2 * kc + t2;
            float p0 = s[tile][0] * inv0, p1 = s[tile][1] * inv0;
            float p2 = s[tile][2] * inv1, p3 = s[tile][3] * inv1;
            __nv_bfloat16 h0 = __float2bfloat16(p0), h1 = __float2bfloat16(p1);
            __nv_bfloat16 h2 = __float2bfloat16(p2), h3 = __float2bfloat16(p3);
            aPh[kc][t2]     = packbf(h0, h1);
            aPh[kc][t2 + 2] = packbf(h2, h3);
            aPl[kc][t2]     = packbf(__float2bfloat16(p0 - __bfloat162float(h0)),
                                     __float2bfloat16(p1 - __bfloat162float(h1)));
            aPl[kc][t2 + 2] = packbf(__float2bfloat16(p2 - __bfloat162float(h2)),
                                     __float2bfloat16(p3 - __bfloat162float(h3)));
        }
    }
#pragma unroll
    for (int kc = 0; kc < 4; kc++) {
        uint32_t t = aPh[kc][1]; aPh[kc][1] = aPh[kc][2]; aPh[kc][2] = t;
        t = aPl[kc][1]; aPl[kc][1] = aPl[kc][2]; aPl[kc][2] = t;
    }

    float o[4][4];
#pragma unroll
    for (int nt = 0; nt < 4; nt++)
#pragma unroll
        for (int r = 0; r < 4; r++) o[nt][r] = 0.f;

#pragma unroll
    for (int part = 0; part < 3; part++) {
        const uint32_t (*Ap)[4] = (part == 1) ? aPl : aPh;
        const uint32_t vB = qkvB + 4 * AB_B + ((part == 2) ? AB_B : 0);
#pragma unroll
        for (int kc = 0; kc < 4; kc++) {
            const uint32_t rowOff = (uint32_t)(min(vR0 + kc * 16, 48) * 80 + vC);
#pragma unroll
            for (int dh = 0; dh < 2; dh++) {
                uint32_t bv[4];
                ldsm4t(bv, vB + rowOff + dh * 32);
                mma16816(o[dh * 2 + 0], Ap[kc], bv[0], bv[1]);
                mma16816(o[dh * 2 + 1], Ap[kc], bv[2], bv[3]);
            }
        }
    }

    const size_t bw = (size_t)(b * 2 + wi);
#pragma unroll
    for (int nt = 0; nt < 4; nt++) {
        int d = h * HDIM + nt * 8 + tg * 2;
        if (r0 < NTOK) {
            size_t off = (bw * NTOK + r0) * DIMC + d;
            __nv_bfloat16 h0 = __float2bfloat16(o[nt][0]);
            __nv_bfloat16 h1 = __float2bfloat16(o[nt][1]);
            *(uint32_t*)(g_aoh + off) = packbf(h0, h1);
            *(uint32_t*)(g_aol + off) =
                packbf(__float2bfloat16(o[nt][0] - __bfloat162float(h0)),
                       __float2bfloat16(o[nt][1] - __bfloat162float(h1)));
        }
        if (r1 < NTOK) {
            size_t off = (bw * NTOK + r1) * DIMC + d;
            __nv_bfloat16 h2 = __float2bfloat16(o[nt][2]);
            __nv_bfloat16 h3 = __float2bfloat16(o[nt][3]);
            *(uint32_t*)(g_aoh + off) = packbf(h2, h3);
            *(uint32_t*)(g_aol + off) =
                packbf(__float2bfloat16(o[nt][2] - __bfloat162float(h2)),
                       __float2bfloat16(o[nt][3] - __bfloat162float(h3)));
        }
    }
}

// ---------------- launch ------------------------------------------------------
extern "C" void kernel_launch(void* const* d_in, const int* in_sizes, int n_in,
                              void* d_out, int out_size) {
    const float* x          = (const float*)d_in[0];
    const float* qkv_w      = (const float*)d_in[1];
    const float* qkv_b      = (const float*)d_in[2];
    const float* proj_w     = (const float*)d_in[3];
    const float* proj_b     = (const float*)d_in[4];
    const float* bias_table = (const float*)d_in[5];
    const int*   rel_idx    = (const int*)d_in[6];
    float* out = (float*)d_out;

    static bool attr_set = false;
    if (!attr_set) {
        cudaFuncSetAttribute(gemm_kernel, cudaFuncAttributeMaxDynamicSharedMemorySize,
                             GEMM_SMEM);
        cudaFuncSetAttribute(attn_kernel, cudaFuncAttributeMaxDynamicSharedMemorySize,
                             ATTN_SMEM);
        attr_set = true;
    }

    prep_kernel<<<640, 256>>>(qkv_w, proj_w, bias_table, rel_idx);

    gemm_kernel<<<T_TOK / GBM, 128, GEMM_SMEM>>>(x, nullptr, qkv_b, 9, 0);

    dim3 g2(2048, NHD);
    attn_kernel<<<g2, 256, ATTN_SMEM>>>();

    gemm_kernel<<<T_TOK / GBM, 128, GEMM_SMEM>>>(nullptr, out, proj_b, 3, 1);
}

// round 17
// speedup vs baseline: 2.0382x; 1.3698x over previous
#include <cuda_runtime.h>
#include <cuda_bf16.h>
#include <cuda_fp16.h>
#include <cstdint>
#include <cstddef>

#define T_TOK 200704          // 4096 * 49 tokens
#define DIMC  192
#define NHD   6
#define HDIM  32
#define NTOK  49
#define NQKV  576
#define SCALEA 0.17677669529663687f
#define BIAS_STRIDE 2404      // 49*49 padded to 16B multiple (floats)

// ---------------- device scratch (static; no runtime allocation) -------------
__device__ __nv_bfloat16 g_qkvh[(size_t)T_TOK * NQKV];   // [b][which][h][tok][d]
__device__ __nv_bfloat16 g_qkvl[(size_t)T_TOK * NQKV];
__device__ __half g_aoh[(size_t)T_TOK * DIMC];           // attn out hi (fp16) [t][c]
__device__ __half g_aol[(size_t)T_TOK * DIMC];           // attn out lo (fp16)
__device__ __half g_wqkvT[NQKV * DIMC];                  // fp16 weights [n][k]
__device__ __half g_wprojT[DIMC * DIMC];
__device__ float g_bias6[NHD * BIAS_STRIDE];

// ---------------- helpers ----------------------------------------------------
__device__ __forceinline__ uint32_t packbf(__nv_bfloat16 a, __nv_bfloat16 b) {
    __nv_bfloat162 t(a, b);
    return *reinterpret_cast<uint32_t*>(&t);
}

__device__ __forceinline__ uint32_t packh(__half a, __half b) {
    __half2 t = __halves2half2(a, b);
    return *reinterpret_cast<uint32_t*>(&t);
}

// bf16 mma (attention)
__device__ __forceinline__ void mma16816(float* c, const uint32_t* a,
                                         uint32_t b0, uint32_t b1) {
    asm volatile(
        "mma.sync.aligned.m16n8k16.row.col.f32.bf16.bf16.f32 "
        "{%0,%1,%2,%3},{%4,%5,%6,%7},{%8,%9},{%0,%1,%2,%3};"
        : "+f"(c[0]), "+f"(c[1]), "+f"(c[2]), "+f"(c[3])
        : "r"(a[0]), "r"(a[1]), "r"(a[2]), "r"(a[3]), "r"(b0), "r"(b1));
}

// fp16 mma (GEMMs)
__device__ __forceinline__ void mmah(float* c, const uint32_t* a,
                                     uint32_t b0, uint32_t b1) {
    asm volatile(
        "mma.sync.aligned.m16n8k16.row.col.f32.f16.f16.f32 "
        "{%0,%1,%2,%3},{%4,%5,%6,%7},{%8,%9},{%0,%1,%2,%3};"
        : "+f"(c[0]), "+f"(c[1]), "+f"(c[2]), "+f"(c[3])
        : "r"(a[0]), "r"(a[1]), "r"(a[2]), "r"(a[3]), "r"(b0), "r"(b1));
}

__device__ __forceinline__ void ldsm4(uint32_t* r, uint32_t addr) {
    asm volatile("ldmatrix.sync.aligned.m8n8.x4.shared.b16 {%0,%1,%2,%3}, [%4];"
                 : "=r"(r[0]), "=r"(r[1]), "=r"(r[2]), "=r"(r[3]) : "r"(addr));
}

__device__ __forceinline__ void ldsm4t(uint32_t* r, uint32_t addr) {
    asm volatile("ldmatrix.sync.aligned.m8n8.x4.trans.shared.b16 {%0,%1,%2,%3}, [%4];"
                 : "=r"(r[0]), "=r"(r[1]), "=r"(r[2]), "=r"(r[3]) : "r"(addr));
}

__device__ __forceinline__ void cpa16(uint32_t smem, const void* gptr) {
    asm volatile("cp.async.cg.shared.global [%0], [%1], 16;\n"
                 :: "r"(smem), "l"(gptr));
}
__device__ __forceinline__ void cp_commit() {
    asm volatile("cp.async.commit_group;\n" ::: "memory");
}
__device__ __forceinline__ void cp_wait0() {
    asm volatile("cp.async.wait_group 0;\n" ::: "memory");
}

__device__ __forceinline__ uint32_t s2u(const void* p) {
    return (uint32_t)__cvta_generic_to_shared(p);
}

// ---------------- prep: fp16 weights + pre-gather bias ------------------------
__global__ void prep_kernel(const float* __restrict__ qkv_w,
                            const float* __restrict__ proj_w,
                            const float* __restrict__ bias_table,
                            const int*   __restrict__ rel_idx) {
    const int n1 = NQKV * DIMC, n2 = DIMC * DIMC, n3 = NHD * NTOK * NTOK;
    for (int i = blockIdx.x * blockDim.x + threadIdx.x; i < n1 + n2 + n3;
         i += gridDim.x * blockDim.x) {
        if (i < n1) {
            int n = i / DIMC, k = i % DIMC;
            g_wqkvT[i] = __float2half(qkv_w[k * NQKV + n]);
        } else if (i < n1 + n2) {
            int j = i - n1;
            int n = j / DIMC, k = j % DIMC;
            g_wprojT[j] = __float2half(proj_w[k * DIMC + n]);
        } else {
            int j = i - n1 - n2;
            int h6 = j / (NTOK * NTOK);
            int rc = j % (NTOK * NTOK);
            g_bias6[h6 * BIAS_STRIDE + rc] = bias_table[rel_idx[rc] * NHD + h6];
        }
    }
}

// ---------------- GEMM (fp16 2-term): C = (Ah+Al)*Wh + bias -------------------
// A (fp16 hi/lo) resident; B (fp16 single) in 64-col chunks, single buffer.
// 4 warps = 2(M) x 2(N); warp tile 32M x 32N; 6 ldsm4 -> 16 MMAs per kk.
// mode 0: A = x fp32 (split in prologue), C -> g_qkvh/l scatter, 9 chunks
// mode 1: A = g_aoh/g_aol fp16 (cp.async), C -> out fp32,        3 chunks
#define GBM   64
#define GSTR  200                        // smem row stride in halves
#define SM_A  (GBM * GSTR)               // 12800 halves per A buffer
#define SM_B  (64 * GSTR)                // 12800 halves for B
#define GEMM_SMEM ((2 * SM_A + SM_B) * 2)   // 76800 bytes

__global__ __launch_bounds__(128, 2)
void gemm_kernel(const float* __restrict__ Ax, float* __restrict__ Cout,
                 const float* __restrict__ bias, int nChunks, int mode) {
    extern __shared__ __half smh[];
    __half* Ah = smh;
    __half* Al = smh + SM_A;
    __half* Bh = smh + 2 * SM_A;

    const __half* Bg = mode ? g_wprojT : g_wqkvT;

    const int tid = threadIdx.x;
    const size_t rbase = (size_t)blockIdx.x * GBM;

    // B chunk 0 (async)
    for (int i = tid; i < 64 * 24; i += 128) {
        int row = i / 24, j = i % 24;
        cpa16(s2u(Bh + row * GSTR + j * 8), Bg + (size_t)row * DIMC + j * 8);
    }
    cp_commit();

    if (mode == 0) {
        // A: fp32 x, convert+split to fp16 hi/lo in smem
        for (int i = tid; i < GBM * 48; i += 128) {
            int row = i / 48, j = i % 48;
            float4 v = *(const float4*)(Ax + (rbase + row) * DIMC + j * 4);
            __half h0 = __float2half(v.x), h1 = __float2half(v.y);
            __half h2 = __float2half(v.z), h3 = __float2half(v.w);
            __half l0 = __float2half(v.x - __half2float(h0));
            __half l1 = __float2half(v.y - __half2float(h1));
            __half l2 = __float2half(v.z - __half2float(h2));
            __half l3 = __float2half(v.w - __half2float(h3));
            *(uint2*)(Ah + row * GSTR + j * 4) = make_uint2(packh(h0, h1), packh(h2, h3));
            *(uint2*)(Al + row * GSTR + j * 4) = make_uint2(packh(l0, l1), packh(l2, l3));
        }
    } else {
        for (int i = tid; i < GBM * 24; i += 128) {
            int row = i / 24, j = i % 24;
            const size_t go = (rbase + row) * DIMC + j * 8;
            cpa16(s2u(Ah + row * GSTR + j * 8), g_aoh + go);
            cpa16(s2u(Al + row * GSTR + j * 8), g_aol + go);
        }
        cp_commit();
    }
    cp_wait0();
    __syncthreads();

    const int lane = tid & 31, warp = tid >> 5;
    const int g = lane >> 2, tg = lane & 3;
    const int m0 = (warp >> 1) * 32;        // 2 warps over M=64
    const int n0 = (warp & 1) * 32;         // 2 warps over 64-col chunk

    const int aRow = m0 + (lane & 15);
    const int aK   = (lane >> 4) * 8;
    const int b4Row = n0 + (lane & 7) + ((lane >> 4) << 3);
    const int bK    = ((lane >> 3) & 1) * 8;

    const uint32_t aBaseH = s2u(Ah + aRow * GSTR + aK);
    const uint32_t aBaseL = aBaseH + SM_A * 2;
    const uint32_t bBase  = s2u(Bh + b4Row * GSTR + bK);
    const uint32_t ROW16 = 16 * GSTR * 2;   // +16 rows in bytes

    for (int c = 0; c < nChunks; c++) {
        float acc[2][4][4];
#pragma unroll
        for (int mt = 0; mt < 2; mt++)
#pragma unroll
            for (int nt = 0; nt < 4; nt++)
#pragma unroll
                for (int r = 0; r < 4; r++) acc[mt][nt][r] = 0.f;

#pragma unroll
        for (int kk = 0; kk < 12; kk++) {
            uint32_t ah[8], al[8], bh[8];
            ldsm4(ah,     aBaseH + kk * 32);
            ldsm4(ah + 4, aBaseH + ROW16 + kk * 32);
            ldsm4(bh,     bBase + kk * 32);
            ldsm4(bh + 4, bBase + ROW16 + kk * 32);
            ldsm4(al,     aBaseL + kk * 32);
            ldsm4(al + 4, aBaseL + ROW16 + kk * 32);
#pragma unroll
            for (int mt = 0; mt < 2; mt++)
#pragma unroll
                for (int nt = 0; nt < 4; nt++)
                    mmah(acc[mt][nt], ah + 4 * mt, bh[2 * nt], bh[2 * nt + 1]);
#pragma unroll
            for (int mt = 0; mt < 2; mt++)
#pragma unroll
                for (int nt = 0; nt < 4; nt++)
                    mmah(acc[mt][nt], al + 4 * mt, bh[2 * nt], bh[2 * nt + 1]);
        }
        __syncthreads();                    // all warps done reading B chunk c

        if (c + 1 < nChunks) {              // overwrite B with next chunk
            for (int i = tid; i < 64 * 24; i += 128) {
                int row = i / 24, j = i % 24;
                cpa16(s2u(Bh + row * GSTR + j * 8),
                      Bg + (size_t)((c + 1) * 64 + row) * DIMC + j * 8);
            }
            cp_commit();
        }

        // epilogue for chunk c (overlaps in-flight cp.async)
        if (mode == 0) {
            const int which = c / 3;
            const int hb = (c % 3) * 2;
#pragma unroll
            for (int mt = 0; mt < 2; mt++)
#pragma unroll
                for (int rr = 0; rr < 2; rr++) {
                    size_t r = rbase + m0 + mt * 16 + g + rr * 8;
                    unsigned bwin = (unsigned)(r / NTOK), tok = (unsigned)(r % NTOK);
                    size_t ob = ((size_t)(bwin * 3 + which) * NHD) * NTOK * HDIM
                                + (size_t)tok * HDIM;
#pragma unroll
                    for (int nt = 0; nt < 4; nt++) {
                        int local = n0 + nt * 8 + tg * 2;
                        int hh = hb + (local >> 5), d = local & 31;
                        float v0 = acc[mt][nt][rr * 2 + 0] + bias[c * 64 + local];
                        float v1 = acc[mt][nt][rr * 2 + 1] + bias[c * 64 + local + 1];
                        __nv_bfloat16 h0 = __float2bfloat16(v0);
                        __nv_bfloat16 h1 = __float2bfloat16(v1);
                        size_t off = ob + (size_t)hh * NTOK * HDIM + d;
                        *(uint32_t*)(g_qkvh + off) = packbf(h0, h1);
                        *(uint32_t*)(g_qkvl + off) =
                            packbf(__float2bfloat16(v0 - __bfloat162float(h0)),
                                   __float2bfloat16(v1 - __bfloat162float(h1)));
                    }
                }
        } else {
#pragma unroll
            for (int mt = 0; mt < 2; mt++)
#pragma unroll
                for (int rr = 0; rr < 2; rr++) {
                    size_t r = rbase + m0 + mt * 16 + g + rr * 8;
#pragma unroll
                    for (int nt = 0; nt < 4; nt++) {
                        int col = c * 64 + n0 + nt * 8 + tg * 2;
                        *(float2*)(Cout + r * DIMC + col) =
                            make_float2(acc[mt][nt][rr * 2 + 0] + bias[col],
                                        acc[mt][nt][rr * 2 + 1] + bias[col + 1]);
                    }
                }
        }

        if (c + 1 < nChunks) {
            cp_wait0();
            __syncthreads();
        }
    }
}

// ---------------- attention: one CTA per (2 windows, head) -------------------
#define ABUF 1960                 // halves per buffer
#define AB_B 3920                 // bytes per buffer
#define ATTN_SMEM (12 * AB_B + BIAS_STRIDE * 4)   // 56656 bytes

__global__ __launch_bounds__(256)
void attn_kernel() {
    extern __shared__ char dsm[];
    __nv_bfloat16* sQKV = (__nv_bfloat16*)dsm;
    float* sBias = (float*)(dsm + 12 * AB_B);

    const int b = blockIdx.x, h = blockIdx.y;   // b = window pair
    const int tid = threadIdx.x;
    const uint32_t sBase = s2u(sQKV);
    const uint32_t sBiasU = s2u(sBias);

    {
        const size_t slabStride = (size_t)NTOK * HDIM;               // 1568
        const float* biasg = g_bias6 + h * BIAS_STRIDE;
        for (int i = tid; i < 12 * 196 + 601; i += 256) {
            if (i < 12 * 196) {
                int s = i / 196, j = i - s * 196;
                int wi = s / 6, sb2 = s - wi * 6;
                int which = sb2 >> 1;
                const size_t base =
                    ((size_t)(b * 2 + wi) * 3 * NHD + h) * slabStride
                    + (size_t)which * NHD * slabStride;
                const __nv_bfloat16* src =
                    ((sb2 & 1) ? g_qkvl : g_qkvh) + base + j * 8;
                cpa16(sBase + s * AB_B + (j >> 2) * 80 + (j & 3) * 16, src);
            } else {
                int j = i - 12 * 196;
                cpa16(sBiasU + j * 16, biasg + j * 4);
            }
        }
        cp_commit();
    }

    const int lane = tid & 31, w = tid >> 5;
    const int wi = w >> 2, wl = w & 3;
    const int g = lane >> 2, tg = lane & 3;
    const uint32_t qkvB = sBase + wi * (6 * AB_B);

    const int qRow = wl * 16 + (lane & 15);
    const uint32_t qOff = (uint32_t)(min(qRow, 48) * 80 + (lane >> 4) * 16);
    const int kR = (lane & 7) + ((lane >> 4) << 3);
    const int kC = ((lane >> 3) & 1) * 16;
    const int vR0 = (lane & 7) + (((lane >> 3) & 1) << 3);
    const int vC = (lane >> 4) * 16;

    cp_wait0();
    __syncthreads();

    float s[8][4];
#pragma unroll
    for (int nt = 0; nt < 8; nt++)
#pragma unroll
        for (int r = 0; r < 4; r++) s[nt][r] = 0.f;

#pragma unroll
    for (int part = 0; part < 3; part++) {
        const uint32_t qB = qkvB + ((part == 1) ? AB_B : 0) + qOff;
        const uint32_t kB = qkvB + 2 * AB_B + ((part == 2) ? AB_B : 0);
#pragma unroll
        for (int kk = 0; kk < 2; kk++) {
            uint32_t a[4];
            ldsm4(a, qB + kk * 32);
#pragma unroll
            for (int p = 0; p < 4; p++) {
                uint32_t bfr[4];
                ldsm4(bfr, kB + (uint32_t)(min(p * 16 + kR, 48) * 80 + kC) + kk * 32);
                mma16816(s[2 * p], a, bfr[0], bfr[1]);
                mma16816(s[2 * p + 1], a, bfr[2], bfr[3]);
            }
        }
    }

    const int r0 = wl * 16 + g, r1 = r0 + 8;
#pragma unroll
    for (int nt = 0; nt < 8; nt++) {
#pragma unroll
        for (int j = 0; j < 2; j++) {
            int col = nt * 8 + tg * 2 + j;
            if (col < NTOK) {
                s[nt][j]     = s[nt][j]     * SCALEA + (r0 < NTOK ? sBias[r0 * NTOK + col] : 0.f);
                s[nt][2 + j] = s[nt][2 + j] * SCALEA + (r1 < NTOK ? sBias[r1 * NTOK + col] : 0.f);
            } else {
                s[nt][j] = -1e30f;
                s[nt][2 + j] = -1e30f;
            }
        }
    }

    float m0 = -1e30f, m1 = -1e30f;
#pragma unroll
    for (int nt = 0; nt < 8; nt++) {
        m0 = fmaxf(m0, fmaxf(s[nt][0], s[nt][1]));
        m1 = fmaxf(m1, fmaxf(s[nt][2], s[nt][3]));
    }
    m0 = fmaxf(m0, __shfl_xor_sync(0xffffffffu, m0, 1));
    m0 = fmaxf(m0, __shfl_xor_sync(0xffffffffu, m0, 2));
    m1 = fmaxf(m1, __shfl_xor_sync(0xffffffffu, m1, 1));
    m1 = fmaxf(m1, __shfl_xor_sync(0xffffffffu, m1, 2));
    float d0 = 0.f, d1 = 0.f;
#pragma unroll
    for (int nt = 0; nt < 8; nt++) {
        s[nt][0] = __expf(s[nt][0] - m0); d0 += s[nt][0];
        s[nt][1] = __expf(s[nt][1] - m0); d0 += s[nt][1];
        s[nt][2] = __expf(s[nt][2] - m1); d1 += s[nt][2];
        s[nt][3] = __expf(s[nt][3] - m1); d1 += s[nt][3];
    }
    d0 += __shfl_xor_sync(0xffffffffu, d0, 1);
    d0 += __shfl_xor_sync(0xffffffffu, d0, 2);
    d1 += __shfl_xor_sync(0xffffffffu, d1, 1);
    d1 += __shfl_xor_sync(0xffffffffu, d1, 2);
    const float inv0 = 1.f / d0, inv1 = 1.f / d1;

    uint32_t aPh[4][4], aPl[4][4];
#pragma unroll
    for (int kc = 0; kc < 4; kc++) {
#pragma unroll
        for (int t2 = 0; t2 < 2; t2++) {
            int tile = 2 * kc + t2;
            float p0 = s[tile][0] * inv0, p1 = s[tile][1] * inv0;
            float p2 = s[tile][2] * inv1, p3 = s[tile][3] * inv1;
            __nv_bfloat16 h0 = __float2bfloat16(p0), h1 = __float2bfloat16(p1);
            __nv_bfloat16 h2 = __float2bfloat16(p2), h3 = __float2bfloat16(p3);
            aPh[kc][t2]     = packbf(h0, h1);
            aPh[kc][t2 + 2] = packbf(h2, h3);
            aPl[kc][t2]     = packbf(__float2bfloat16(p0 - __bfloat162float(h0)),
                                     __float2bfloat16(p1 - __bfloat162float(h1)));
            aPl[kc][t2 + 2] = packbf(__float2bfloat16(p2 - __bfloat162float(h2)),
                                     __float2bfloat16(p3 - __bfloat162float(h3)));
        }
    }
#pragma unroll
    for (int kc = 0; kc < 4; kc++) {
        uint32_t t = aPh[kc][1]; aPh[kc][1] = aPh[kc][2]; aPh[kc][2] = t;
        t = aPl[kc][1]; aPl[kc][1] = aPl[kc][2]; aPl[kc][2] = t;
    }

    float o[4][4];
#pragma unroll
    for (int nt = 0; nt < 4; nt++)
#pragma unroll
        for (int r = 0; r < 4; r++) o[nt][r] = 0.f;

#pragma unroll
    for (int part = 0; part < 3; part++) {
        const uint32_t (*Ap)[4] = (part == 1) ? aPl : aPh;
        const uint32_t vB = qkvB + 4 * AB_B + ((part == 2) ? AB_B : 0);
#pragma unroll
        for (int kc = 0; kc < 4; kc++) {
            const uint32_t rowOff = (uint32_t)(min(vR0 + kc * 16, 48) * 80 + vC);
#pragma unroll
            for (int dh = 0; dh < 2; dh++) {
                uint32_t bv[4];
                ldsm4t(bv, vB + rowOff + dh * 32);
                mma16816(o[dh * 2 + 0], Ap[kc], bv[0], bv[1]);
                mma16816(o[dh * 2 + 1], Ap[kc], bv[2], bv[3]);
            }
        }
    }

    // ---- store fp16 hi/lo (feeds fp16 gemm2 A operand) ----
    const size_t bw = (size_t)(b * 2 + wi);
#pragma unroll
    for (int nt = 0; nt < 4; nt++) {
        int d = h * HDIM + nt * 8 + tg * 2;
        if (r0 < NTOK) {
            size_t off = (bw * NTOK + r0) * DIMC + d;
            __half h0 = __float2half(o[nt][0]);
            __half h1 = __float2half(o[nt][1]);
            *(uint32_t*)(g_aoh + off) = packh(h0, h1);
            *(uint32_t*)(g_aol + off) =
                packh(__float2half(o[nt][0] - __half2float(h0)),
                      __float2half(o[nt][1] - __half2float(h1)));
        }
        if (r1 < NTOK) {
            size_t off = (bw * NTOK + r1) * DIMC + d;
            __half h2 = __float2half(o[nt][2]);
            __half h3 = __float2half(o[nt][3]);
            *(uint32_t*)(g_aoh + off) = packh(h2, h3);
            *(uint32_t*)(g_aol + off) =
                packh(__float2half(o[nt][2] - __half2float(h2)),
                      __float2half(o[nt][3] - __half2float(h3)));
        }
    }
}

// ---------------- launch ------------------------------------------------------
extern "C" void kernel_launch(void* const* d_in, const int* in_sizes, int n_in,
                              void* d_out, int out_size) {
    const float* x          = (const float*)d_in[0];
    const float* qkv_w      = (const float*)d_in[1];
    const float* qkv_b      = (const float*)d_in[2];
    const float* proj_w     = (const float*)d_in[3];
    const float* proj_b     = (const float*)d_in[4];
    const float* bias_table = (const float*)d_in[5];
    const int*   rel_idx    = (const int*)d_in[6];
    float* out = (float*)d_out;

    static bool attr_set = false;
    if (!attr_set) {
        cudaFuncSetAttribute(gemm_kernel, cudaFuncAttributeMaxDynamicSharedMemorySize,
                             GEMM_SMEM);
        cudaFuncSetAttribute(attn_kernel, cudaFuncAttributeMaxDynamicSharedMemorySize,
                             ATTN_SMEM);
        attr_set = true;
    }

    prep_kernel<<<640, 256>>>(qkv_w, proj_w, bias_table, rel_idx);

    gemm_kernel<<<T_TOK / GBM, 128, GEMM_SMEM>>>(x, nullptr, qkv_b, 9, 0);

    dim3 g2(2048, NHD);
    attn_kernel<<<g2, 256, ATTN_SMEM>>>();

    gemm_kernel<<<T_TOK / GBM, 128, GEMM_SMEM>>>(nullptr, out, proj_b, 3, 1);
}